// round 11
// baseline (speedup 1.0000x reference)
#include <cuda_runtime.h>
#include <cuda_bf16.h>
#include <math.h>
#include <stddef.h>
#include <stdint.h>

// B=256, T=512, V=64(65 rows), E=128, H=256, 3H=768, D=2

// ---------------- PTX helpers (baseline ISA only: sm_80-era, safe on sm_103) ----------------
__device__ __forceinline__ uint32_t smem_to_u32(const void* p) {
    uint32_t a;
    asm("{ .reg .u64 t; cvta.to.shared.u64 t, %1; cvt.u32.u64 %0, t; }" : "=r"(a) : "l"(p));
    return a;
}
__device__ __forceinline__ void cp16(uint32_t s, const void* g) {
    asm volatile("cp.async.cg.shared.global [%0], [%1], 16;" :: "r"(s), "l"(g) : "memory");
}
#define CP_COMMIT() asm volatile("cp.async.commit_group;" ::: "memory")
#define CP_WAIT(n)  asm volatile("cp.async.wait_group %0;" :: "n"(n) : "memory")
#define LDSM_X4(r0, r1, r2, r3, addr) \
    asm volatile("ldmatrix.sync.aligned.m8n8.x4.shared.b16 {%0,%1,%2,%3}, [%4];" \
        : "=r"(r0), "=r"(r1), "=r"(r2), "=r"(r3) : "r"(addr))
#define LDSM_X2(r0, r1, addr) \
    asm volatile("ldmatrix.sync.aligned.m8n8.x2.shared.b16 {%0,%1}, [%2];" \
        : "=r"(r0), "=r"(r1) : "r"(addr))

__device__ __forceinline__ void mma16816(float* c, const uint32_t* a, const uint32_t* b) {
    asm volatile(
        "mma.sync.aligned.m16n8k16.row.col.f32.bf16.bf16.f32 "
        "{%0,%1,%2,%3}, {%4,%5,%6,%7}, {%8,%9}, {%0,%1,%2,%3};"
        : "+f"(c[0]), "+f"(c[1]), "+f"(c[2]), "+f"(c[3])
        : "r"(a[0]), "r"(a[1]), "r"(a[2]), "r"(a[3]), "r"(b[0]), "r"(b[1]));
}

#define SWZ128(b) ((b) ^ (((b) >> 3) & 0x70))

// pack 4 floats -> hi/lo bf16 pairs (8 bytes each)
__device__ __forceinline__ void split4(float4 v, uint2& hi, uint2& lo) {
    __nv_bfloat16 a0 = __float2bfloat16(v.x), a1 = __float2bfloat16(v.y);
    __nv_bfloat16 a2 = __float2bfloat16(v.z), a3 = __float2bfloat16(v.w);
    __nv_bfloat16 l0 = __float2bfloat16(v.x - __bfloat162float(a0));
    __nv_bfloat16 l1 = __float2bfloat16(v.y - __bfloat162float(a1));
    __nv_bfloat16 l2 = __float2bfloat16(v.z - __bfloat162float(a2));
    __nv_bfloat16 l3 = __float2bfloat16(v.w - __bfloat162float(a3));
    __nv_bfloat162 h01 = __halves2bfloat162(a0, a1), h23 = __halves2bfloat162(a2, a3);
    __nv_bfloat162 m01 = __halves2bfloat162(l0, l1), m23 = __halves2bfloat162(l2, l3);
    hi.x = *(uint32_t*)&h01; hi.y = *(uint32_t*)&h23;
    lo.x = *(uint32_t*)&m01; lo.y = *(uint32_t*)&m23;
}

// pack 2 floats -> hi/lo bf16x2 words
__device__ __forceinline__ void split2(float a, float b, uint32_t& hi, uint32_t& lo) {
    __nv_bfloat16 a0 = __float2bfloat16(a), a1 = __float2bfloat16(b);
    __nv_bfloat16 l0 = __float2bfloat16(a - __bfloat162float(a0));
    __nv_bfloat16 l1 = __float2bfloat16(b - __bfloat162float(a1));
    __nv_bfloat162 h = __halves2bfloat162(a0, a1);
    __nv_bfloat162 l = __halves2bfloat162(l0, l1);
    hi = *(uint32_t*)&h; lo = *(uint32_t*)&l;
}

__device__ __forceinline__ float fsig(float x) {
    return __fdividef(1.f, 1.f + __expf(-x));
}
__device__ __forceinline__ float ftanh(float x) {
    return __fdividef(2.f, 1.f + __expf(-2.f*x)) - 1.f;
}

// ---------------- static scratch ----------------
__device__ float d_ptab [2*65*768];
__device__ float d_xp1  [2*512*256*768];
__device__ float d_fc1p [512*256*128];
__device__ __nv_bfloat16 d_hpinghi[2*2*256*256];
__device__ __nv_bfloat16 d_hpinglo[2*2*256*256];
__device__ __nv_bfloat16 d_h1hi[67108864], d_h1lo[67108864];
__device__ __nv_bfloat16 d_h2hi[67108864], d_h2lo[67108864];
__device__ __nv_bfloat16 d_wihhi[786432], d_wihlo[786432];
__device__ __nv_bfloat16 d_W1hi[33554432], d_W1lo[33554432];
__device__ unsigned d_flags[4096];   // [16 groups][8 slots][32 pad]

__global__ void reset_bar_kernel() {
    d_flags[blockIdx.x*256 + threadIdx.x] = 0u;
}

// consumer-side poll: 8 lanes poll the 8 peer flags of the group (no sleep)
__device__ __forceinline__ void poll_group(int gid, unsigned target, int lane) {
    if (lane < 8) {
        const unsigned* f = d_flags + (gid*8 + lane)*32;
        unsigned v;
        do {
            asm volatile("ld.global.acquire.gpu.u32 %0, [%1];" : "=r"(v) : "l"(f));
        } while (v < target);
    }
    __syncwarp();
}

// ---------------- L0 proj table ----------------
__global__ void __launch_bounds__(256) proj0_kernel(const float* __restrict__ emb,
                                                    const float* __restrict__ wih,
                                                    const float* __restrict__ bih) {
    const int d = blockIdx.x / 65;
    const int v = blockIdx.x % 65;
    __shared__ float es[128];
    if (threadIdx.x < 128) es[threadIdx.x] = emb[v*128 + threadIdx.x];
    __syncthreads();
    for (int g = threadIdx.x; g < 768; g += 256) {
        const float* w = wih + ((size_t)d*768 + g)*128;
        float s = bih[d*768 + g];
        #pragma unroll 4
        for (int e = 0; e < 128; e++) s += es[e]*__ldg(w + e);
        d_ptab[((size_t)d*65 + v)*768 + g] = s;
    }
}

// ---------------- fp32 -> bf16 hi/lo split (weights only) ----------------
__global__ void __launch_bounds__(256) split_kernel(const float* __restrict__ x,
        __nv_bfloat16* __restrict__ hi, __nv_bfloat16* __restrict__ lo, size_t n4) {
    size_t i = (size_t)blockIdx.x*256 + threadIdx.x;
    size_t stride = (size_t)gridDim.x*256;
    for (; i < n4; i += stride) {
        float4 v = __ldg((const float4*)x + i);
        uint2 h, l;
        split4(v, h, l);
        ((uint2*)hi)[i] = h;
        ((uint2*)lo)[i] = l;
    }
}

// ---------------- MMA recurrence (both layers) ----------------
// 128 CTAs = dir(2) x batch-slice(8 x 32 rows) x unit-slice(8 x 32 units)
// W rows interleaved lr = wn*24 + gate*8 + jl so each thread's C fragments hold
// complete (r,z,n) triples -> nonlinearity fully in registers (no G smem).
// SMEM: WHI @0 (49152) | WLO @49152 | HHI @98304 (16384) | HLO @114688 (16384)
#define RECM_SMEM (131072 + 1024)

template<int LAYER>
__global__ void __launch_bounds__(256, 1) rec_mma_kernel(
    const int* __restrict__ inputs,
    const float* __restrict__ w_hh,
    const float* __restrict__ b_hh) {
    extern __shared__ char sm_raw[];
    __shared__ __align__(8) float bhh_s[96];
    const uint32_t raw  = smem_to_u32(sm_raw);
    const uint32_t base = (raw + 1023u) & ~1023u;
    char* sb = sm_raw + (base - raw);

    const int bid = blockIdx.x;
    const int dir = bid >> 6;
    const int rem = bid & 63;
    const int bs  = rem >> 3;
    const int us  = rem & 7;
    const int b0  = bs * 32;
    const int j0  = us * 32;
    const int gid = dir*8 + bs;
    const int tid = threadIdx.x;
    const int lane = tid & 31;
    const int wid  = tid >> 5;

    // ---- one-time: W_hh slice -> bf16 hi/lo swizzled smem, interleaved rows ----
    {
        const int k0 = (tid & 7) * 32;
        #pragma unroll
        for (int rr = 0; rr < 3; rr++) {
            const int lr = rr*32 + (tid >> 3);
            const int wnl = lr / 24;
            const int rem24 = lr - wnl*24;
            const int gg = rem24 >> 3;
            const int jj = wnl*8 + (rem24 & 7);
            const float* src = w_hh + ((size_t)dir*768 + gg*256 + j0 + jj)*256 + k0;
            const uint32_t cb = (uint32_t)(k0 >> 6)*12288u + (uint32_t)lr*128u + (uint32_t)(k0 & 63)*2u;
            #pragma unroll
            for (int q = 0; q < 8; q++) {
                float4 v = __ldg((const float4*)src + q);
                uint2 h, l;
                split4(v, h, l);
                uint32_t off = SWZ128(cb + q*8);
                *(uint2*)(sb + off)          = h;
                *(uint2*)(sb + 49152u + off) = l;
            }
        }
    }
    if (tid < 96) {
        const int lr = tid;
        const int wnl = lr / 24;
        const int rem24 = lr - wnl*24;
        const int gg = rem24 >> 3;
        const int jj = wnl*8 + (rem24 & 7);
        bhh_s[lr] = b_hh[dir*768 + gg*256 + j0 + jj];
    }
    // zero h tiles
    for (int i = tid; i < 2048; i += 256)
        ((uint4*)(sb + 98304))[i] = make_uint4(0,0,0,0);
    __syncthreads();

    // MMA lane mappings
    const int wm = wid >> 2, wn = wid & 3;
    const int lrow = lane & 15, kseg = lane >> 4;
    const int g8 = lane >> 3, lr8 = lane & 7;
    const int nrx4 = ((g8 >> 1) & 1)*8 + lr8;
    const int ksx4 = g8 & 1;
    const int lx = lane & 15;
    const int rowb2 = lx & 7, kh2 = (lx >> 3) & 1;
    const int l4 = lane >> 2, qh = lane & 3;

    // per-thread output mapping: rows {r0g, r0g+8}, units {jg0, jg0+1}
    const int r0g = b0 + wm*16 + l4;
    const int jg0 = j0 + wn*8 + 2*qh;

    const float2 b_r = *(const float2*)&bhh_s[wn*24      + 2*qh];
    const float2 b_z = *(const float2*)&bhh_s[wn*24 + 8  + 2*qh];
    const float2 b_n = *(const float2*)&bhh_s[wn*24 + 16 + 2*qh];

    float hp[2][2] = {{0.f,0.f},{0.f,0.f}};

    __nv_bfloat16* obh = (LAYER == 0) ? d_h1hi : d_h2hi;
    __nv_bfloat16* obl = (LAYER == 0) ? d_h1lo : d_h2lo;
    const unsigned LB = (unsigned)(LAYER * 512);

    const int cr  = tid >> 3;      // consumer row 0..31
    const int cseg = tid & 7;      // 16B segment within 64-col chunk

    for (int s_ = 0; s_ < 512; s_++) {
        // prefetch x-projections (independent of peers -> before poll)
        const int t_in = (dir == 0) ? s_ : (511 - s_);
        float2 xv[2][3];
        #pragma unroll
        for (int h = 0; h < 2; h++) {
            const int row = r0g + h*8;
            if (LAYER == 0) {
                const int tok = __ldg(inputs + row*512 + t_in);
                const float* pt = d_ptab + ((size_t)dir*65 + tok)*768 + jg0;
                xv[h][0] = __ldg((const float2*)(pt));
                xv[h][1] = __ldg((const float2*)(pt + 256));
                xv[h][2] = __ldg((const float2*)(pt + 512));
            } else {
                const float* xp = d_xp1 + ((size_t)dir*131072 + (size_t)t_in*256 + row)*768 + jg0;
                xv[h][0] = __ldg((const float2*)(xp));
                xv[h][1] = __ldg((const float2*)(xp + 256));
                xv[h][2] = __ldg((const float2*)(xp + 512));
            }
        }

        if (s_ > 0) {
            poll_group(gid, LB + (unsigned)s_, lane);
            const int par = s_ & 1;
            const __nv_bfloat16* ghi = d_hpinghi + (((size_t)dir*2 + par)*256 + b0)*256;
            const __nv_bfloat16* glo = d_hpinglo + (((size_t)dir*2 + par)*256 + b0)*256;
            #pragma unroll
            for (int ck = 0; ck < 4; ck++) {
                uint32_t dst = SWZ128((uint32_t)(ck*4096 + cr*128 + cseg*16));
                size_t go = (size_t)cr*256 + (size_t)ck*64 + (size_t)cseg*8;
                cp16(base + 98304u  + dst, ghi + go);
                cp16(base + 114688u + dst, glo + go);
                if (ck == 1) CP_COMMIT();
            }
            CP_COMMIT();
        }

        float c[3][4];
        #pragma unroll
        for (int fn = 0; fn < 3; fn++)
            #pragma unroll
            for (int q = 0; q < 4; q++) c[fn][q] = 0.f;

        // ---- MMA halves: chunks {0,1} then {2,3} (overlap cp.async) ----
        #pragma unroll
        for (int half = 0; half < 2; half++) {
            if (s_ > 0) { if (half == 0) { CP_WAIT(1); } else { CP_WAIT(0); } }
            __syncthreads();
            #pragma unroll
            for (int ks = 0; ks < 8; ks++) {
                const int cks = half*8 + ks;
                const int ck = cks >> 2, ki = cks & 3;
                const uint32_t ain = base + 98304u + (uint32_t)ck*4096u +
                    SWZ128((uint32_t)((wm*16 + lrow)*128 + ki*32 + kseg*16));
                uint32_t ah[4], al[4];
                LDSM_X4(ah[0], ah[1], ah[2], ah[3], ain);
                LDSM_X4(al[0], al[1], al[2], al[3], ain + 16384u);
                const uint32_t bcb = base + (uint32_t)ck*12288u;
                const uint32_t b4 = bcb +
                    SWZ128((uint32_t)((wn*24 + nrx4)*128 + ki*32 + ksx4*16));
                const uint32_t b2 = bcb +
                    SWZ128((uint32_t)((wn*24 + 16 + rowb2)*128 + ki*32 + kh2*16));
                uint32_t bh[3][2], bl[3][2];
                LDSM_X4(bh[0][0], bh[0][1], bh[1][0], bh[1][1], b4);
                LDSM_X2(bh[2][0], bh[2][1], b2);
                LDSM_X4(bl[0][0], bl[0][1], bl[1][0], bl[1][1], b4 + 49152u);
                LDSM_X2(bl[2][0], bl[2][1], b2 + 49152u);
                #pragma unroll
                for (int fn = 0; fn < 3; fn++) {
                    mma16816(c[fn], ah, bh[fn]);
                    mma16816(c[fn], ah, bl[fn]);
                    mma16816(c[fn], al, bh[fn]);
                }
            }
        }

        // ---- nonlinearity + h update, fully in registers ----
        const int parn = (s_ + 1) & 1;
        #pragma unroll
        for (int h = 0; h < 2; h++) {
            const int row = r0g + h*8;
            const float* xr = (const float*)&xv[h][0];
            const float* xz = (const float*)&xv[h][1];
            const float* xn = (const float*)&xv[h][2];
            const float* brp = (const float*)&b_r;
            const float* bzp = (const float*)&b_z;
            const float* bnp = (const float*)&b_n;
            float hn[2];
            #pragma unroll
            for (int e = 0; e < 2; e++) {
                float r = fsig(xr[e] + c[0][2*h + e] + brp[e]);
                float z = fsig(xz[e] + c[1][2*h + e] + bzp[e]);
                float n = ftanh(xn[e] + r*(c[2][2*h + e] + bnp[e]));
                hn[e] = (1.f - z)*n + z*hp[h][e];
                hp[h][e] = hn[e];
            }
            uint32_t whi, wlo;
            split2(hn[0], hn[1], whi, wlo);
            size_t oo = ((size_t)t_in*256 + row)*512 + (size_t)dir*256 + jg0;
            *(uint32_t*)(obh + oo) = whi;
            *(uint32_t*)(obl + oo) = wlo;
            if (s_ != 511) {
                size_t po = (((size_t)dir*2 + parn)*256 + row)*256 + jg0;
                asm volatile("st.global.cg.u32 [%0], %1;" :: "l"(d_hpinghi + po), "r"(whi));
                asm volatile("st.global.cg.u32 [%0], %1;" :: "l"(d_hpinglo + po), "r"(wlo));
            }
        }
        if (s_ != 511) {
            __threadfence();
            __syncthreads();
            if (tid == 0) {
                asm volatile("st.global.cg.u32 [%0], %1;"
                    :: "l"(d_flags + (gid*8 + us)*32), "r"(LB + (unsigned)(s_ + 1)));
            }
        }
    }
}

// ---------------- split-bf16 warp-MMA GEMM (mma.sync m16n8k16 bf16) ----------------
// MODE 0: xp1 = h1 @ wih1^T + bias.  grid (1024 mtiles, 6 ntiles, 2 dirs)
// MODE 1: fc1 partials per t.        grid (2 mtiles, 1, 512 t)
#define MMA_DSMEM (2*65536 + 1024)

template<int MODE>
__global__ void __launch_bounds__(256) mma_gemm_kernel(
    const __nv_bfloat16* __restrict__ Ah, const __nv_bfloat16* __restrict__ Al,
    const __nv_bfloat16* __restrict__ Bh, const __nv_bfloat16* __restrict__ Bl,
    const float* __restrict__ bias, float* __restrict__ outp) {
    extern __shared__ char dsm_raw[];
    const uint32_t raw  = smem_to_u32(dsm_raw);
    const uint32_t base = (raw + 1023u) & ~1023u;

    const int tid  = threadIdx.x;
    const int lane = tid & 31;
    const int wid  = tid >> 5;
    const int wm   = wid >> 2;
    const int wn   = wid & 3;

    size_t arow0, brow0, bstride, bk0;
    if (MODE == 0) {
        arow0 = (size_t)blockIdx.x * 128;
        brow0 = (size_t)blockIdx.z * 768 + (size_t)blockIdx.y * 128;
        bstride = 512; bk0 = 0;
    } else {
        arow0 = (size_t)blockIdx.z * 256 + (size_t)blockIdx.x * 128;
        brow0 = 0;
        bstride = 262144; bk0 = (size_t)blockIdx.z * 512;
    }

    float c[4][4][4];
    #pragma unroll
    for (int fm = 0; fm < 4; fm++)
    #pragma unroll
    for (int fn = 0; fn < 4; fn++)
    #pragma unroll
    for (int q = 0; q < 4; q++) c[fm][fn][q] = 0.f;

    auto issue = [&](int kc, int buf) {
        const uint32_t sbb = base + (uint32_t)buf*65536u;
        #pragma unroll
        for (int v = 0; v < 4; v++) {
            int vv = tid + v*256;
            int r = vv >> 3, seg = vv & 7;
            uint32_t sw = SWZ128((uint32_t)(r*128 + seg*16));
            size_t k  = (size_t)kc*64 + (size_t)seg*8;
            size_t ga = (arow0 + r)*512 + k;
            size_t gb = (brow0 + r)*bstride + bk0 + k;
            cp16(sbb +          sw, Ah + ga);
            cp16(sbb + 16384u + sw, Al + ga);
            cp16(sbb + 32768u + sw, Bh + gb);
            cp16(sbb + 49152u + sw, Bl + gb);
        }
    };

    issue(0, 0); CP_COMMIT();

    for (int kc = 0; kc < 8; kc++) {
        if (kc < 7) {
            issue(kc + 1, (kc + 1) & 1); CP_COMMIT();
            CP_WAIT(1);
        } else {
            CP_WAIT(0);
        }
        __syncthreads();

        const uint32_t sbb = base + (uint32_t)(kc & 1)*65536u;
        const int lrow = lane & 15, kseg = lane >> 4;
        const int g = lane >> 3, lr = lane & 7;
        const int nrow = ((g >> 1) & 1)*8 + lr;
        const int ks2 = g & 1;

        #pragma unroll
        for (int ki = 0; ki < 4; ki++) {
            uint32_t ahf[4][4], alf[4][4];
            #pragma unroll
            for (int fm = 0; fm < 4; fm++) {
                uint32_t off = SWZ128((uint32_t)((wm*64 + fm*16 + lrow)*128 + ki*32 + kseg*16));
                LDSM_X4(ahf[fm][0], ahf[fm][1], ahf[fm][2], ahf[fm][3], sbb + off);
                LDSM_X4(alf[fm][0], alf[fm][1], alf[fm][2], alf[fm][3], sbb + 16384u + off);
            }
            uint32_t bhf[4][2], blf[4][2];
            #pragma unroll
            for (int fp = 0; fp < 2; fp++) {
                uint32_t off = SWZ128((uint32_t)((wn*32 + fp*16 + nrow)*128 + ki*32 + ks2*16));
                LDSM_X4(bhf[fp*2][0], bhf[fp*2][1], bhf[fp*2+1][0], bhf[fp*2+1][1], sbb + 32768u + off);
                LDSM_X4(blf[fp*2][0], blf[fp*2][1], blf[fp*2+1][0], blf[fp*2+1][1], sbb + 49152u + off);
            }
            #pragma unroll
            for (int fm = 0; fm < 4; fm++)
            #pragma unroll
            for (int fn = 0; fn < 4; fn++) {
                mma16816(c[fm][fn], ahf[fm], bhf[fn]);
                mma16816(c[fm][fn], ahf[fm], blf[fn]);
                mma16816(c[fm][fn], alf[fm], bhf[fn]);
            }
        }
        __syncthreads();
    }

    const int l4 = lane >> 2;
    const int l2 = (lane & 3)*2;
    #pragma unroll
    for (int fm = 0; fm < 4; fm++) {
        const int mr0 = wm*64 + fm*16 + l4;
        #pragma unroll
        for (int fn = 0; fn < 4; fn++) {
            const int col = wn*32 + fn*8 + l2;
            if (MODE == 0) {
                const int gcol = blockIdx.y*128 + col;
                float2 bv = *(const float2*)(bias + blockIdx.z*768 + gcol);
                size_t m0 = (size_t)blockIdx.z*131072 + (size_t)blockIdx.x*128 + mr0;
                *(float2*)(outp + m0*768 + gcol)       = make_float2(c[fm][fn][0] + bv.x, c[fm][fn][1] + bv.y);
                *(float2*)(outp + (m0 + 8)*768 + gcol) = make_float2(c[fm][fn][2] + bv.x, c[fm][fn][3] + bv.y);
            } else {
                size_t m0 = (size_t)blockIdx.z*256 + (size_t)blockIdx.x*128 + mr0;
                *(float2*)(outp + m0*128 + col)       = make_float2(c[fm][fn][0], c[fm][fn][1]);
                *(float2*)(outp + (m0 + 8)*128 + col) = make_float2(c[fm][fn][2], c[fm][fn][3]);
            }
        }
    }
}

// ---------------- final reduce + MLP head ----------------
__global__ void __launch_bounds__(128) fc_reduce_kernel(
    const float* __restrict__ b1, const float* __restrict__ W2,
    const float* __restrict__ b2, float* __restrict__ out) {
    const int b = blockIdx.x;
    const int o = threadIdx.x;
    const float* p = d_fc1p + (size_t)b*128 + o;
    float s0 = 0.f, s1 = 0.f, s2 = 0.f, s3 = 0.f;
    #pragma unroll 4
    for (int t = 0; t < 512; t += 4) {
        s0 += p[(size_t)(t+0)*32768];
        s1 += p[(size_t)(t+1)*32768];
        s2 += p[(size_t)(t+2)*32768];
        s3 += p[(size_t)(t+3)*32768];
    }
    float s = b1[o] + ((s0 + s1) + (s2 + s3));
    float v = s > 0.f ? s : 0.01f*s;
    float c = v * __ldg(W2 + o);
    __shared__ float red[128];
    red[o] = c;
    __syncthreads();
    for (int st = 64; st > 0; st >>= 1) {
        if (o < st) red[o] += red[o + st];
        __syncthreads();
    }
    if (o == 0) out[b] = 1.f/(1.f + expf(-(red[0] + b2[0])));
}

// ---------------- launch ----------------
extern "C" void kernel_launch(void* const* d_in, const int* in_sizes, int n_in,
                              void* d_out, int out_size) {
    const int*   inputs = (const int*)  d_in[0];
    const float* emb    = (const float*)d_in[1];
    const float* wih0   = (const float*)d_in[2];
    const float* whh0   = (const float*)d_in[3];
    const float* bih0   = (const float*)d_in[4];
    const float* bhh0   = (const float*)d_in[5];
    const float* wih1   = (const float*)d_in[6];
    const float* whh1   = (const float*)d_in[7];
    const float* bih1   = (const float*)d_in[8];
    const float* bhh1   = (const float*)d_in[9];
    const float* W1     = (const float*)d_in[10];
    const float* b1     = (const float*)d_in[11];
    const float* W2     = (const float*)d_in[12];
    const float* b2     = (const float*)d_in[13];
    float* out = (float*)d_out;

    cudaFuncSetAttribute((const void*)rec_mma_kernel<0>,
                         cudaFuncAttributeMaxDynamicSharedMemorySize, RECM_SMEM);
    cudaFuncSetAttribute((const void*)rec_mma_kernel<1>,
                         cudaFuncAttributeMaxDynamicSharedMemorySize, RECM_SMEM);
    cudaFuncSetAttribute((const void*)mma_gemm_kernel<0>,
                         cudaFuncAttributeMaxDynamicSharedMemorySize, MMA_DSMEM);
    cudaFuncSetAttribute((const void*)mma_gemm_kernel<1>,
                         cudaFuncAttributeMaxDynamicSharedMemorySize, MMA_DSMEM);

    __nv_bfloat16 *h1hi, *h1lo, *h2hi, *h2lo, *wihhi, *wihlo, *W1hi, *W1lo;
    cudaGetSymbolAddress((void**)&h1hi, d_h1hi);
    cudaGetSymbolAddress((void**)&h1lo, d_h1lo);
    cudaGetSymbolAddress((void**)&h2hi, d_h2hi);
    cudaGetSymbolAddress((void**)&h2lo, d_h2lo);
    cudaGetSymbolAddress((void**)&wihhi, d_wihhi);
    cudaGetSymbolAddress((void**)&wihlo, d_wihlo);
    cudaGetSymbolAddress((void**)&W1hi, d_W1hi);
    cudaGetSymbolAddress((void**)&W1lo, d_W1lo);
    float *xp1p, *fc1p;
    cudaGetSymbolAddress((void**)&xp1p, d_xp1);
    cudaGetSymbolAddress((void**)&fc1p, d_fc1p);

    proj0_kernel<<<130, 256>>>(emb, wih0, bih0);
    split_kernel<<<768, 256>>>(wih1, wihhi, wihlo, 196608);
    split_kernel<<<4096, 256>>>(W1, W1hi, W1lo, 8388608);
    reset_bar_kernel<<<16, 256>>>();
    rec_mma_kernel<0><<<128, 256, RECM_SMEM>>>(inputs, whh0, bhh0);
    mma_gemm_kernel<0><<<dim3(1024, 6, 2), 256, MMA_DSMEM>>>(h1hi, h1lo, wihhi, wihlo, bih1, xp1p);
    rec_mma_kernel<1><<<128, 256, RECM_SMEM>>>(inputs, whh1, bhh1);
    mma_gemm_kernel<1><<<dim3(2, 1, 512), 256, MMA_DSMEM>>>(h2hi, h2lo, W1hi, W1lo, nullptr, fc1p);
    fc_reduce_kernel<<<256, 128>>>(b1, W2, b2, out);
}

// round 12
// speedup vs baseline: 1.0371x; 1.0371x over previous
#include <cuda_runtime.h>
#include <cuda_bf16.h>
#include <math.h>
#include <stddef.h>
#include <stdint.h>

// B=256, T=512, V=64(65 rows), E=128, H=256, 3H=768, D=2

// ---------------- PTX helpers (baseline ISA only: sm_80-era, safe on sm_103) ----------------
__device__ __forceinline__ uint32_t smem_to_u32(const void* p) {
    uint32_t a;
    asm("{ .reg .u64 t; cvta.to.shared.u64 t, %1; cvt.u32.u64 %0, t; }" : "=r"(a) : "l"(p));
    return a;
}
__device__ __forceinline__ void cp16(uint32_t s, const void* g) {
    asm volatile("cp.async.cg.shared.global [%0], [%1], 16;" :: "r"(s), "l"(g) : "memory");
}
#define CP_COMMIT() asm volatile("cp.async.commit_group;" ::: "memory")
#define CP_WAIT(n)  asm volatile("cp.async.wait_group %0;" :: "n"(n) : "memory")
#define LDSM_X4(r0, r1, r2, r3, addr) \
    asm volatile("ldmatrix.sync.aligned.m8n8.x4.shared.b16 {%0,%1,%2,%3}, [%4];" \
        : "=r"(r0), "=r"(r1), "=r"(r2), "=r"(r3) : "r"(addr))
#define LDSM_X2(r0, r1, addr) \
    asm volatile("ldmatrix.sync.aligned.m8n8.x2.shared.b16 {%0,%1}, [%2];" \
        : "=r"(r0), "=r"(r1) : "r"(addr))

__device__ __forceinline__ void mma16816(float* c, const uint32_t* a, const uint32_t* b) {
    asm volatile(
        "mma.sync.aligned.m16n8k16.row.col.f32.bf16.bf16.f32 "
        "{%0,%1,%2,%3}, {%4,%5,%6,%7}, {%8,%9}, {%0,%1,%2,%3};"
        : "+f"(c[0]), "+f"(c[1]), "+f"(c[2]), "+f"(c[3])
        : "r"(a[0]), "r"(a[1]), "r"(a[2]), "r"(a[3]), "r"(b[0]), "r"(b[1]));
}

#define SWZ128(b) ((b) ^ (((b) >> 3) & 0x70))

// pack 4 floats -> hi/lo bf16 pairs (8 bytes each)
__device__ __forceinline__ void split4(float4 v, uint2& hi, uint2& lo) {
    __nv_bfloat16 a0 = __float2bfloat16(v.x), a1 = __float2bfloat16(v.y);
    __nv_bfloat16 a2 = __float2bfloat16(v.z), a3 = __float2bfloat16(v.w);
    __nv_bfloat16 l0 = __float2bfloat16(v.x - __bfloat162float(a0));
    __nv_bfloat16 l1 = __float2bfloat16(v.y - __bfloat162float(a1));
    __nv_bfloat16 l2 = __float2bfloat16(v.z - __bfloat162float(a2));
    __nv_bfloat16 l3 = __float2bfloat16(v.w - __bfloat162float(a3));
    __nv_bfloat162 h01 = __halves2bfloat162(a0, a1), h23 = __halves2bfloat162(a2, a3);
    __nv_bfloat162 m01 = __halves2bfloat162(l0, l1), m23 = __halves2bfloat162(l2, l3);
    hi.x = *(uint32_t*)&h01; hi.y = *(uint32_t*)&h23;
    lo.x = *(uint32_t*)&m01; lo.y = *(uint32_t*)&m23;
}

__device__ __forceinline__ float fsig(float x) {
    return __fdividef(1.f, 1.f + __expf(-x));
}
__device__ __forceinline__ float ftanh(float x) {
    return __fdividef(2.f, 1.f + __expf(-2.f*x)) - 1.f;
}

// ---------------- static scratch ----------------
__device__ float d_ptab [2*65*768];
__device__ float d_xp1  [2*512*256*768];
__device__ float d_fc1p [512*256*128];
__device__ __nv_bfloat16 d_h1hi[67108864], d_h1lo[67108864];
__device__ __nv_bfloat16 d_h2hi[67108864], d_h2lo[67108864];
__device__ __nv_bfloat16 d_wihhi[786432], d_wihlo[786432];
__device__ __nv_bfloat16 d_W1hi[33554432], d_W1lo[33554432];
__device__ unsigned d_flags[4096];   // [16 groups][8 slots][32 pad]

__global__ void reset_bar_kernel() {
    d_flags[blockIdx.x*256 + threadIdx.x] = 0u;
}

// consumer-side poll: 8 lanes poll the 8 peer flags of the group
__device__ __forceinline__ void poll_group(int gid, unsigned target, int lane) {
    if (lane < 8) {
        const unsigned* f = d_flags + (gid*8 + lane)*32;
        unsigned v;
        while (true) {
            asm volatile("ld.global.acquire.gpu.u32 %0, [%1];" : "=r"(v) : "l"(f));
            if (v >= target) break;
            __nanosleep(20);
        }
    }
    __syncwarp();
}

// ---------------- L0 proj table ----------------
__global__ void __launch_bounds__(256) proj0_kernel(const float* __restrict__ emb,
                                                    const float* __restrict__ wih,
                                                    const float* __restrict__ bih) {
    const int d = blockIdx.x / 65;
    const int v = blockIdx.x % 65;
    __shared__ float es[128];
    if (threadIdx.x < 128) es[threadIdx.x] = emb[v*128 + threadIdx.x];
    __syncthreads();
    for (int g = threadIdx.x; g < 768; g += 256) {
        const float* w = wih + ((size_t)d*768 + g)*128;
        float s = bih[d*768 + g];
        #pragma unroll 4
        for (int e = 0; e < 128; e++) s += es[e]*__ldg(w + e);
        d_ptab[((size_t)d*65 + v)*768 + g] = s;
    }
}

// ---------------- fp32 -> bf16 hi/lo split (weights only) ----------------
__global__ void __launch_bounds__(256) split_kernel(const float* __restrict__ x,
        __nv_bfloat16* __restrict__ hi, __nv_bfloat16* __restrict__ lo, size_t n4) {
    size_t i = (size_t)blockIdx.x*256 + threadIdx.x;
    size_t stride = (size_t)gridDim.x*256;
    for (; i < n4; i += stride) {
        float4 v = __ldg((const float4*)x + i);
        uint2 h, l;
        split4(v, h, l);
        ((uint2*)hi)[i] = h;
        ((uint2*)lo)[i] = l;
    }
}

// ---------------- MMA recurrence (both layers) ----------------
// 128 CTAs = dir(2) x batch-slice(8 x 32 rows) x unit-slice(8 x 32 units)
// Per step: G[32 x 96] = h[32 x 256] @ Wslice[96 x 256]^T via split-bf16 3-pass mma.
// h exchanged through the per-timestep OUTPUT buffer (bf16 hi/lo, row stride 512):
// producer stores its slice once; peers cp.async it at t_prev next step.
// SMEM layout (1024-aligned base):
//   WHI  @ 0      : 4 chunks x (96 rows x 128B)   = 49152
//   WLO  @ 49152  : 49152
//   HHI  @ 98304  : 4 chunks x (32 rows x 128B)   = 16384
//   HLO  @ 114688 : 16384
//   G    @ 131072 : 32 x 100 floats               = 12800
//   HPREV@ 143872 : 32 x 36 floats                = 4608
#define RECM_SMEM (148480 + 1024)

template<int LAYER>
__global__ void __launch_bounds__(256, 1) rec_mma_kernel(
    const int* __restrict__ inputs,
    const float* __restrict__ w_hh,
    const float* __restrict__ b_hh) {
    extern __shared__ char sm_raw[];
    __shared__ float bhh_s[96];
    const uint32_t raw  = smem_to_u32(sm_raw);
    const uint32_t base = (raw + 1023u) & ~1023u;
    char* sb = sm_raw + (base - raw);
    float* Gs    = (float*)(sb + 131072);
    float* Hprev = (float*)(sb + 143872);

    const int bid = blockIdx.x;
    const int dir = bid >> 6;
    const int rem = bid & 63;
    const int bs  = rem >> 3;
    const int us  = rem & 7;
    const int b0  = bs * 32;
    const int j0  = us * 32;
    const int gid = dir*8 + bs;
    const int tid = threadIdx.x;
    const int lane = tid & 31;
    const int wid  = tid >> 5;

    // ---- one-time: W_hh slice -> bf16 hi/lo swizzled smem (gate-interleaved rows) ----
    {
        const int k0 = (tid & 7) * 32;
        #pragma unroll
        for (int rr = 0; rr < 3; rr++) {
            const int lr = rr*32 + (tid >> 3);
            const int g  = lr >> 5;
            const float* src = w_hh + ((size_t)dir*768 + g*256 + j0 + (lr & 31))*256 + k0;
            const uint32_t cb = (uint32_t)(k0 >> 6)*12288u + (uint32_t)lr*128u + (uint32_t)(k0 & 63)*2u;
            #pragma unroll
            for (int q = 0; q < 8; q++) {
                float4 v = __ldg((const float4*)src + q);
                uint2 h, l;
                split4(v, h, l);
                uint32_t off = SWZ128(cb + q*8);
                *(uint2*)(sb + off)          = h;
                *(uint2*)(sb + 49152u + off) = l;
            }
        }
    }
    if (tid < 96) bhh_s[tid] = b_hh[dir*768 + (tid>>5)*256 + j0 + (tid & 31)];
    // zero h tiles + hprev
    for (int i = tid; i < 2048; i += 256)
        ((uint4*)(sb + 98304))[i] = make_uint4(0,0,0,0);
    for (int i = tid; i < 1152; i += 256)
        Hprev[i] = 0.f;
    __syncthreads();

    // per-thread nonlinearity mapping
    const int bb = tid >> 3;
    const int ju = (tid & 7) * 4;
    const int bg = b0 + bb;

    // MMA lane mappings
    const int wm = wid >> 2, wn = wid & 3;
    const int lrow = lane & 15, kseg = lane >> 4;
    const int g8 = lane >> 3, lr8 = lane & 7;
    const int nrx4 = ((g8 >> 1) & 1)*8 + lr8;
    const int ksx4 = g8 & 1;
    const int lx = lane & 15;
    const int rowb2 = lx & 7, kh2 = (lx >> 3) & 1;

    __nv_bfloat16* obh = (LAYER == 0) ? d_h1hi : d_h2hi;
    __nv_bfloat16* obl = (LAYER == 0) ? d_h1lo : d_h2lo;
    const unsigned LB = (unsigned)(LAYER * 512);

    for (int s_ = 0; s_ < 512; s_++) {
        // prefetch x-projections (independent of peers -> issue before poll)
        const int t_in = (dir == 0) ? s_ : (511 - s_);
        float4 xr4, xz4, xn4;
        if (LAYER == 0) {
            const int tok = __ldg(inputs + bg*512 + t_in);
            const float* pt = d_ptab + ((size_t)dir*65 + tok)*768 + j0 + ju;
            xr4 = __ldg((const float4*)(pt));
            xz4 = __ldg((const float4*)(pt + 256));
            xn4 = __ldg((const float4*)(pt + 512));
        } else {
            const float* xp = d_xp1 + ((size_t)dir*131072 + (size_t)t_in*256 + bg)*768 + j0 + ju;
            xr4 = __ldg((const float4*)(xp));
            xz4 = __ldg((const float4*)(xp + 256));
            xn4 = __ldg((const float4*)(xp + 512));
        }

        if (s_ > 0) {
            poll_group(gid, LB + (unsigned)s_, lane);
            // read peers' h from the OUTPUT buffer at t_prev (row stride 512)
            const int t_prev = (dir == 0) ? (s_ - 1) : (512 - s_);
            const __nv_bfloat16* ghi = obh + ((size_t)t_prev*256 + b0)*512 + (size_t)dir*256;
            const __nv_bfloat16* glo = obl + ((size_t)t_prev*256 + b0)*512 + (size_t)dir*256;
            #pragma unroll
            for (int v = 0; v < 4; v++) {
                int vv = tid + v*256;          // 0..1023
                int r   = vv >> 5;             // 0..31 (batch row)
                int ks16 = vv & 31;            // 16B segment (8 bf16)
                uint32_t dst = SWZ128((uint32_t)((ks16 >> 3)*4096 + r*128 + (ks16 & 7)*16));
                size_t gofs = (size_t)r*512 + (size_t)ks16*8;
                cp16(base + 98304u  + dst, ghi + gofs);
                cp16(base + 114688u + dst, glo + gofs);
            }
            CP_COMMIT(); CP_WAIT(0);
            __syncthreads();
        }

        // ---- MMA: G = h @ Wslice^T, 3-pass split ----
        float c[3][4];
        #pragma unroll
        for (int fn = 0; fn < 3; fn++)
            #pragma unroll
            for (int q = 0; q < 4; q++) c[fn][q] = 0.f;

        #pragma unroll
        for (int ks = 0; ks < 16; ks++) {
            const int ck = ks >> 2, ki = ks & 3;
            const uint32_t ain = base + 98304u + (uint32_t)ck*4096u +
                SWZ128((uint32_t)((wm*16 + lrow)*128 + ki*32 + kseg*16));
            uint32_t ah[4], al[4];
            LDSM_X4(ah[0], ah[1], ah[2], ah[3], ain);
            LDSM_X4(al[0], al[1], al[2], al[3], ain + 16384u);
            const uint32_t bcb = base + (uint32_t)ck*12288u;
            const uint32_t b4 = bcb +
                SWZ128((uint32_t)((wn*24 + nrx4)*128 + ki*32 + ksx4*16));
            const uint32_t b2 = bcb +
                SWZ128((uint32_t)((wn*24 + 16 + rowb2)*128 + ki*32 + kh2*16));
            uint32_t bh[3][2], bl[3][2];
            LDSM_X4(bh[0][0], bh[0][1], bh[1][0], bh[1][1], b4);
            LDSM_X2(bh[2][0], bh[2][1], b2);
            LDSM_X4(bl[0][0], bl[0][1], bl[1][0], bl[1][1], b4 + 49152u);
            LDSM_X2(bl[2][0], bl[2][1], b2 + 49152u);
            #pragma unroll
            for (int fn = 0; fn < 3; fn++) {
                mma16816(c[fn], ah, bh[fn]);
                mma16816(c[fn], ah, bl[fn]);
                mma16816(c[fn], al, bh[fn]);
            }
        }

        // write G to smem
        {
            const int l4 = lane >> 2, l2 = (lane & 3)*2;
            #pragma unroll
            for (int fn = 0; fn < 3; fn++) {
                const int col = wn*24 + fn*8 + l2;
                *(float2*)&Gs[(wm*16 + l4)*100 + col]     = make_float2(c[fn][0], c[fn][1]);
                *(float2*)&Gs[(wm*16 + l4 + 8)*100 + col] = make_float2(c[fn][2], c[fn][3]);
            }
        }
        __syncthreads();

        // ---- nonlinearity + h update ----
        {
            float4 gr = *(const float4*)&Gs[bb*100 + ju];
            float4 gz = *(const float4*)&Gs[bb*100 + 32 + ju];
            float4 gn = *(const float4*)&Gs[bb*100 + 64 + ju];
            float4 hp = *(const float4*)&Hprev[bb*36 + ju];
            float hn[4];
            const float* xr = &xr4.x;
            const float* xz = &xz4.x;
            const float* xn = &xn4.x;
            const float* grp = &gr.x;
            const float* gzp = &gz.x;
            const float* gnp = &gn.x;
            const float* hpp = &hp.x;
            #pragma unroll
            for (int i = 0; i < 4; i++) {
                float r = fsig(xr[i] + grp[i] + bhh_s[     ju + i]);
                float z = fsig(xz[i] + gzp[i] + bhh_s[32 + ju + i]);
                float n = ftanh(xn[i] + r*(gnp[i] + bhh_s[64 + ju + i]));
                hn[i] = (1.f - z)*n + z*hpp[i];
            }
            float4 hv = make_float4(hn[0], hn[1], hn[2], hn[3]);
            *(float4*)&Hprev[bb*36 + ju] = hv;
            uint2 hhi, hlo;
            split4(hv, hhi, hlo);
            size_t oo = ((size_t)t_in*256 + bg)*512 + (size_t)dir*256 + j0 + ju;
            asm volatile("st.global.cg.v2.u32 [%0], {%1,%2};" :: "l"(obh + oo), "r"(hhi.x), "r"(hhi.y));
            asm volatile("st.global.cg.v2.u32 [%0], {%1,%2};" :: "l"(obl + oo), "r"(hlo.x), "r"(hlo.y));
        }
        if (s_ != 511) {
            __threadfence();
            __syncthreads();
            if (tid == 0) {
                asm volatile("st.global.release.gpu.u32 [%0], %1;"
                    :: "l"(d_flags + (gid*8 + us)*32), "r"(LB + (unsigned)(s_ + 1)));
            }
        }
    }
}

// ---------------- split-bf16 warp-MMA GEMM (mma.sync m16n8k16 bf16) ----------------
// MODE 0: xp1 = h1 @ wih1^T + bias.  grid (1024 mtiles, 6 ntiles, 2 dirs)
// MODE 1: fc1 partials per t.        grid (2 mtiles, 1, 512 t)
#define MMA_DSMEM (2*65536 + 1024)

template<int MODE>
__global__ void __launch_bounds__(256) mma_gemm_kernel(
    const __nv_bfloat16* __restrict__ Ah, const __nv_bfloat16* __restrict__ Al,
    const __nv_bfloat16* __restrict__ Bh, const __nv_bfloat16* __restrict__ Bl,
    const float* __restrict__ bias, float* __restrict__ outp) {
    extern __shared__ char dsm_raw[];
    const uint32_t raw  = smem_to_u32(dsm_raw);
    const uint32_t base = (raw + 1023u) & ~1023u;

    const int tid  = threadIdx.x;
    const int lane = tid & 31;
    const int wid  = tid >> 5;
    const int wm   = wid >> 2;
    const int wn   = wid & 3;

    size_t arow0, brow0, bstride, bk0;
    if (MODE == 0) {
        arow0 = (size_t)blockIdx.x * 128;
        brow0 = (size_t)blockIdx.z * 768 + (size_t)blockIdx.y * 128;
        bstride = 512; bk0 = 0;
    } else {
        arow0 = (size_t)blockIdx.z * 256 + (size_t)blockIdx.x * 128;
        brow0 = 0;
        bstride = 262144; bk0 = (size_t)blockIdx.z * 512;
    }

    float c[4][4][4];
    #pragma unroll
    for (int fm = 0; fm < 4; fm++)
    #pragma unroll
    for (int fn = 0; fn < 4; fn++)
    #pragma unroll
    for (int q = 0; q < 4; q++) c[fm][fn][q] = 0.f;

    auto issue = [&](int kc, int buf) {
        const uint32_t sbb = base + (uint32_t)buf*65536u;
        #pragma unroll
        for (int v = 0; v < 4; v++) {
            int vv = tid + v*256;
            int r = vv >> 3, seg = vv & 7;
            uint32_t sw = SWZ128((uint32_t)(r*128 + seg*16));
            size_t k  = (size_t)kc*64 + (size_t)seg*8;
            size_t ga = (arow0 + r)*512 + k;
            size_t gb = (brow0 + r)*bstride + bk0 + k;
            cp16(sbb +          sw, Ah + ga);
            cp16(sbb + 16384u + sw, Al + ga);
            cp16(sbb + 32768u + sw, Bh + gb);
            cp16(sbb + 49152u + sw, Bl + gb);
        }
    };

    issue(0, 0); CP_COMMIT();

    for (int kc = 0; kc < 8; kc++) {
        if (kc < 7) {
            issue(kc + 1, (kc + 1) & 1); CP_COMMIT();
            CP_WAIT(1);
        } else {
            CP_WAIT(0);
        }
        __syncthreads();

        const uint32_t sbb = base + (uint32_t)(kc & 1)*65536u;
        const int lrow = lane & 15, kseg = lane >> 4;
        const int g = lane >> 3, lr = lane & 7;
        const int nrow = ((g >> 1) & 1)*8 + lr;
        const int ks2 = g & 1;

        #pragma unroll
        for (int ki = 0; ki < 4; ki++) {
            uint32_t ahf[4][4], alf[4][4];
            #pragma unroll
            for (int fm = 0; fm < 4; fm++) {
                uint32_t off = SWZ128((uint32_t)((wm*64 + fm*16 + lrow)*128 + ki*32 + kseg*16));
                LDSM_X4(ahf[fm][0], ahf[fm][1], ahf[fm][2], ahf[fm][3], sbb + off);
                LDSM_X4(alf[fm][0], alf[fm][1], alf[fm][2], alf[fm][3], sbb + 16384u + off);
            }
            uint32_t bhf[4][2], blf[4][2];
            #pragma unroll
            for (int fp = 0; fp < 2; fp++) {
                uint32_t off = SWZ128((uint32_t)((wn*32 + fp*16 + nrow)*128 + ki*32 + ks2*16));
                LDSM_X4(bhf[fp*2][0], bhf[fp*2][1], bhf[fp*2+1][0], bhf[fp*2+1][1], sbb + 32768u + off);
                LDSM_X4(blf[fp*2][0], blf[fp*2][1], blf[fp*2+1][0], blf[fp*2+1][1], sbb + 49152u + off);
            }
            #pragma unroll
            for (int fm = 0; fm < 4; fm++)
            #pragma unroll
            for (int fn = 0; fn < 4; fn++) {
                mma16816(c[fm][fn], ahf[fm], bhf[fn]);
                mma16816(c[fm][fn], ahf[fm], blf[fn]);
                mma16816(c[fm][fn], alf[fm], bhf[fn]);
            }
        }
        __syncthreads();
    }

    const int l4 = lane >> 2;
    const int l2 = (lane & 3)*2;
    #pragma unroll
    for (int fm = 0; fm < 4; fm++) {
        const int mr0 = wm*64 + fm*16 + l4;
        #pragma unroll
        for (int fn = 0; fn < 4; fn++) {
            const int col = wn*32 + fn*8 + l2;
            if (MODE == 0) {
                const int gcol = blockIdx.y*128 + col;
                float2 bv = *(const float2*)(bias + blockIdx.z*768 + gcol);
                size_t m0 = (size_t)blockIdx.z*131072 + (size_t)blockIdx.x*128 + mr0;
                *(float2*)(outp + m0*768 + gcol)       = make_float2(c[fm][fn][0] + bv.x, c[fm][fn][1] + bv.y);
                *(float2*)(outp + (m0 + 8)*768 + gcol) = make_float2(c[fm][fn][2] + bv.x, c[fm][fn][3] + bv.y);
            } else {
                size_t m0 = (size_t)blockIdx.z*256 + (size_t)blockIdx.x*128 + mr0;
                *(float2*)(outp + m0*128 + col)       = make_float2(c[fm][fn][0], c[fm][fn][1]);
                *(float2*)(outp + (m0 + 8)*128 + col) = make_float2(c[fm][fn][2], c[fm][fn][3]);
            }
        }
    }
}

// ---------------- final reduce + MLP head ----------------
__global__ void __launch_bounds__(128) fc_reduce_kernel(
    const float* __restrict__ b1, const float* __restrict__ W2,
    const float* __restrict__ b2, float* __restrict__ out) {
    const int b = blockIdx.x;
    const int o = threadIdx.x;
    const float* p = d_fc1p + (size_t)b*128 + o;
    float s0 = 0.f, s1 = 0.f, s2 = 0.f, s3 = 0.f;
    #pragma unroll 4
    for (int t = 0; t < 512; t += 4) {
        s0 += p[(size_t)(t+0)*32768];
        s1 += p[(size_t)(t+1)*32768];
        s2 += p[(size_t)(t+2)*32768];
        s3 += p[(size_t)(t+3)*32768];
    }
    float s = b1[o] + ((s0 + s1) + (s2 + s3));
    float v = s > 0.f ? s : 0.01f*s;
    float c = v * __ldg(W2 + o);
    __shared__ float red[128];
    red[o] = c;
    __syncthreads();
    for (int st = 64; st > 0; st >>= 1) {
        if (o < st) red[o] += red[o + st];
        __syncthreads();
    }
    if (o == 0) out[b] = 1.f/(1.f + expf(-(red[0] + b2[0])));
}

// ---------------- launch ----------------
extern "C" void kernel_launch(void* const* d_in, const int* in_sizes, int n_in,
                              void* d_out, int out_size) {
    const int*   inputs = (const int*)  d_in[0];
    const float* emb    = (const float*)d_in[1];
    const float* wih0   = (const float*)d_in[2];
    const float* whh0   = (const float*)d_in[3];
    const float* bih0   = (const float*)d_in[4];
    const float* bhh0   = (const float*)d_in[5];
    const float* wih1   = (const float*)d_in[6];
    const float* whh1   = (const float*)d_in[7];
    const float* bih1   = (const float*)d_in[8];
    const float* bhh1   = (const float*)d_in[9];
    const float* W1     = (const float*)d_in[10];
    const float* b1     = (const float*)d_in[11];
    const float* W2     = (const float*)d_in[12];
    const float* b2     = (const float*)d_in[13];
    float* out = (float*)d_out;

    cudaFuncSetAttribute((const void*)rec_mma_kernel<0>,
                         cudaFuncAttributeMaxDynamicSharedMemorySize, RECM_SMEM);
    cudaFuncSetAttribute((const void*)rec_mma_kernel<1>,
                         cudaFuncAttributeMaxDynamicSharedMemorySize, RECM_SMEM);
    cudaFuncSetAttribute((const void*)mma_gemm_kernel<0>,
                         cudaFuncAttributeMaxDynamicSharedMemorySize, MMA_DSMEM);
    cudaFuncSetAttribute((const void*)mma_gemm_kernel<1>,
                         cudaFuncAttributeMaxDynamicSharedMemorySize, MMA_DSMEM);

    __nv_bfloat16 *h1hi, *h1lo, *h2hi, *h2lo, *wihhi, *wihlo, *W1hi, *W1lo;
    cudaGetSymbolAddress((void**)&h1hi, d_h1hi);
    cudaGetSymbolAddress((void**)&h1lo, d_h1lo);
    cudaGetSymbolAddress((void**)&h2hi, d_h2hi);
    cudaGetSymbolAddress((void**)&h2lo, d_h2lo);
    cudaGetSymbolAddress((void**)&wihhi, d_wihhi);
    cudaGetSymbolAddress((void**)&wihlo, d_wihlo);
    cudaGetSymbolAddress((void**)&W1hi, d_W1hi);
    cudaGetSymbolAddress((void**)&W1lo, d_W1lo);
    float *xp1p, *fc1p;
    cudaGetSymbolAddress((void**)&xp1p, d_xp1);
    cudaGetSymbolAddress((void**)&fc1p, d_fc1p);

    proj0_kernel<<<130, 256>>>(emb, wih0, bih0);
    split_kernel<<<768, 256>>>(wih1, wihhi, wihlo, 196608);
    split_kernel<<<4096, 256>>>(W1, W1hi, W1lo, 8388608);
    reset_bar_kernel<<<16, 256>>>();
    rec_mma_kernel<0><<<128, 256, RECM_SMEM>>>(inputs, whh0, bhh0);
    mma_gemm_kernel<0><<<dim3(1024, 6, 2), 256, MMA_DSMEM>>>(h1hi, h1lo, wihhi, wihlo, bih1, xp1p);
    rec_mma_kernel<1><<<128, 256, RECM_SMEM>>>(inputs, whh1, bhh1);
    mma_gemm_kernel<1><<<dim3(2, 1, 512), 256, MMA_DSMEM>>>(h2hi, h2lo, W1hi, W1lo, nullptr, fc1p);
    fc_reduce_kernel<<<256, 128>>>(b1, W2, b2, out);
}

// round 13
// speedup vs baseline: 1.0488x; 1.0113x over previous
#include <cuda_runtime.h>
#include <cuda_bf16.h>
#include <math.h>
#include <stddef.h>
#include <stdint.h>

// B=256, T=512, V=64(65 rows), E=128, H=256, 3H=768, D=2

// ---------------- PTX helpers (baseline ISA only: sm_80-era, safe on sm_103) ----------------
__device__ __forceinline__ uint32_t smem_to_u32(const void* p) {
    uint32_t a;
    asm("{ .reg .u64 t; cvta.to.shared.u64 t, %1; cvt.u32.u64 %0, t; }" : "=r"(a) : "l"(p));
    return a;
}
__device__ __forceinline__ void cp16(uint32_t s, const void* g) {
    asm volatile("cp.async.cg.shared.global [%0], [%1], 16;" :: "r"(s), "l"(g) : "memory");
}
#define CP_COMMIT() asm volatile("cp.async.commit_group;" ::: "memory")
#define CP_WAIT(n)  asm volatile("cp.async.wait_group %0;" :: "n"(n) : "memory")
#define LDSM_X4(r0, r1, r2, r3, addr) \
    asm volatile("ldmatrix.sync.aligned.m8n8.x4.shared.b16 {%0,%1,%2,%3}, [%4];" \
        : "=r"(r0), "=r"(r1), "=r"(r2), "=r"(r3) : "r"(addr))
#define LDSM_X2(r0, r1, addr) \
    asm volatile("ldmatrix.sync.aligned.m8n8.x2.shared.b16 {%0,%1}, [%2];" \
        : "=r"(r0), "=r"(r1) : "r"(addr))

__device__ __forceinline__ void mma16816(float* c, const uint32_t* a, const uint32_t* b) {
    asm volatile(
        "mma.sync.aligned.m16n8k16.row.col.f32.bf16.bf16.f32 "
        "{%0,%1,%2,%3}, {%4,%5,%6,%7}, {%8,%9}, {%0,%1,%2,%3};"
        : "+f"(c[0]), "+f"(c[1]), "+f"(c[2]), "+f"(c[3])
        : "r"(a[0]), "r"(a[1]), "r"(a[2]), "r"(a[3]), "r"(b[0]), "r"(b[1]));
}

#define SWZ128(b) ((b) ^ (((b) >> 3) & 0x70))

// pack 4 floats -> hi/lo bf16 pairs (8 bytes each)
__device__ __forceinline__ void split4(float4 v, uint2& hi, uint2& lo) {
    __nv_bfloat16 a0 = __float2bfloat16(v.x), a1 = __float2bfloat16(v.y);
    __nv_bfloat16 a2 = __float2bfloat16(v.z), a3 = __float2bfloat16(v.w);
    __nv_bfloat16 l0 = __float2bfloat16(v.x - __bfloat162float(a0));
    __nv_bfloat16 l1 = __float2bfloat16(v.y - __bfloat162float(a1));
    __nv_bfloat16 l2 = __float2bfloat16(v.z - __bfloat162float(a2));
    __nv_bfloat16 l3 = __float2bfloat16(v.w - __bfloat162float(a3));
    __nv_bfloat162 h01 = __halves2bfloat162(a0, a1), h23 = __halves2bfloat162(a2, a3);
    __nv_bfloat162 m01 = __halves2bfloat162(l0, l1), m23 = __halves2bfloat162(l2, l3);
    hi.x = *(uint32_t*)&h01; hi.y = *(uint32_t*)&h23;
    lo.x = *(uint32_t*)&m01; lo.y = *(uint32_t*)&m23;
}

__device__ __forceinline__ float tanh_ap(float x) {
    float y;
    asm("tanh.approx.f32 %0, %1;" : "=f"(y) : "f"(x));
    return y;
}
// sigmoid via HW tanh: sig(x) = 0.5*tanh(0.5x) + 0.5  (1 MUFU instead of 2)
__device__ __forceinline__ float fsig(float x) {
    return fmaf(tanh_ap(0.5f*x), 0.5f, 0.5f);
}
// accurate-ish tanh for the n gate (additive path)
__device__ __forceinline__ float ftanh(float x) {
    return __fdividef(2.f, 1.f + __expf(-2.f*x)) - 1.f;
}

// ---------------- static scratch ----------------
__device__ float d_ptab [2*65*768];
__device__ float d_xp1  [2*512*256*768];
__device__ float d_fc1p [512*256*128];
__device__ __nv_bfloat16 d_h1hi[67108864], d_h1lo[67108864];
__device__ __nv_bfloat16 d_h2hi[67108864], d_h2lo[67108864];
__device__ __nv_bfloat16 d_wihhi[786432], d_wihlo[786432];
__device__ __nv_bfloat16 d_W1hi[33554432], d_W1lo[33554432];
__device__ unsigned d_flags[4096];   // [16 groups][8 slots][32 pad]

__global__ void reset_bar_kernel() {
    d_flags[blockIdx.x*256 + threadIdx.x] = 0u;
}

// consumer-side poll: 8 lanes poll the 8 peer flags of the group
__device__ __forceinline__ void poll_group(int gid, unsigned target, int lane) {
    if (lane < 8) {
        const unsigned* f = d_flags + (gid*8 + lane)*32;
        unsigned v;
        while (true) {
            asm volatile("ld.global.acquire.gpu.u32 %0, [%1];" : "=r"(v) : "l"(f));
            if (v >= target) break;
            __nanosleep(20);
        }
    }
    __syncwarp();
}

// ---------------- L0 proj table ----------------
__global__ void __launch_bounds__(256) proj0_kernel(const float* __restrict__ emb,
                                                    const float* __restrict__ wih,
                                                    const float* __restrict__ bih) {
    const int d = blockIdx.x / 65;
    const int v = blockIdx.x % 65;
    __shared__ float es[128];
    if (threadIdx.x < 128) es[threadIdx.x] = emb[v*128 + threadIdx.x];
    __syncthreads();
    for (int g = threadIdx.x; g < 768; g += 256) {
        const float* w = wih + ((size_t)d*768 + g)*128;
        float s = bih[d*768 + g];
        #pragma unroll 4
        for (int e = 0; e < 128; e++) s += es[e]*__ldg(w + e);
        d_ptab[((size_t)d*65 + v)*768 + g] = s;
    }
}

// ---------------- fp32 -> bf16 hi/lo split (weights only) ----------------
__global__ void __launch_bounds__(256) split_kernel(const float* __restrict__ x,
        __nv_bfloat16* __restrict__ hi, __nv_bfloat16* __restrict__ lo, size_t n4) {
    size_t i = (size_t)blockIdx.x*256 + threadIdx.x;
    size_t stride = (size_t)gridDim.x*256;
    for (; i < n4; i += stride) {
        float4 v = __ldg((const float4*)x + i);
        uint2 h, l;
        split4(v, h, l);
        ((uint2*)hi)[i] = h;
        ((uint2*)lo)[i] = l;
    }
}

// ---------------- MMA recurrence (both layers) ----------------
// 128 CTAs = dir(2) x batch-slice(8 x 32 rows) x unit-slice(8 x 32 units)
// Per step: G[32 x 96] = h[32 x 256] @ Wslice[96 x 256]^T via split-bf16 3-pass mma.
// W-hi fragments are hoisted into registers (96/thread, loaded once): the MMA
// loop was smem-BW bound (~327KB/step/CTA); this removes ~98KB of it.
// SMEM layout (1024-aligned base):
//   WHI  @ 0      : 49152 (only read during init preload)
//   WLO  @ 49152  : 49152
//   HHI  @ 98304  : 16384
//   HLO  @ 114688 : 16384
//   G    @ 131072 : 32 x 100 floats = 12800
//   HPREV@ 143872 : 32 x 36 floats  = 4608
#define RECM_SMEM (148480 + 1024)

template<int LAYER>
__global__ void __launch_bounds__(256, 1) rec_mma_kernel(
    const int* __restrict__ inputs,
    const float* __restrict__ w_hh,
    const float* __restrict__ b_hh) {
    extern __shared__ char sm_raw[];
    __shared__ float bhh_s[96];
    const uint32_t raw  = smem_to_u32(sm_raw);
    const uint32_t base = (raw + 1023u) & ~1023u;
    char* sb = sm_raw + (base - raw);
    float* Gs    = (float*)(sb + 131072);
    float* Hprev = (float*)(sb + 143872);

    const int bid = blockIdx.x;
    const int dir = bid >> 6;
    const int rem = bid & 63;
    const int bs  = rem >> 3;
    const int us  = rem & 7;
    const int b0  = bs * 32;
    const int j0  = us * 32;
    const int gid = dir*8 + bs;
    const int tid = threadIdx.x;
    const int lane = tid & 31;
    const int wid  = tid >> 5;

    // ---- one-time: W_hh slice -> bf16 hi/lo swizzled smem (gate-interleaved rows) ----
    {
        const int k0 = (tid & 7) * 32;
        #pragma unroll
        for (int rr = 0; rr < 3; rr++) {
            const int lr = rr*32 + (tid >> 3);
            const int g  = lr >> 5;
            const float* src = w_hh + ((size_t)dir*768 + g*256 + j0 + (lr & 31))*256 + k0;
            const uint32_t cb = (uint32_t)(k0 >> 6)*12288u + (uint32_t)lr*128u + (uint32_t)(k0 & 63)*2u;
            #pragma unroll
            for (int q = 0; q < 8; q++) {
                float4 v = __ldg((const float4*)src + q);
                uint2 h, l;
                split4(v, h, l);
                uint32_t off = SWZ128(cb + q*8);
                *(uint2*)(sb + off)          = h;
                *(uint2*)(sb + 49152u + off) = l;
            }
        }
    }
    if (tid < 96) bhh_s[tid] = b_hh[dir*768 + (tid>>5)*256 + j0 + (tid & 31)];
    // zero h tiles + hprev
    for (int i = tid; i < 2048; i += 256)
        ((uint4*)(sb + 98304))[i] = make_uint4(0,0,0,0);
    for (int i = tid; i < 1152; i += 256)
        Hprev[i] = 0.f;
    __syncthreads();

    // per-thread nonlinearity mapping
    const int bb = tid >> 3;
    const int ju = (tid & 7) * 4;
    const int bg = b0 + bb;

    // MMA lane mappings
    const int wm = wid >> 2, wn = wid & 3;
    const int lrow = lane & 15, kseg = lane >> 4;
    const int g8 = lane >> 3, lr8 = lane & 7;
    const int nrx4 = ((g8 >> 1) & 1)*8 + lr8;
    const int ksx4 = g8 & 1;
    const int lx = lane & 15;
    const int rowb2 = lx & 7, kh2 = (lx >> 3) & 1;

    // ---- hoist W-hi B-fragments into registers (step-invariant, 96 regs) ----
    uint32_t Bh4[16][4], Bh2[16][2];
    #pragma unroll
    for (int ks = 0; ks < 16; ks++) {
        const int ck = ks >> 2, ki = ks & 3;
        const uint32_t bcb = base + (uint32_t)ck*12288u;
        const uint32_t b4 = bcb +
            SWZ128((uint32_t)((wn*24 + nrx4)*128 + ki*32 + ksx4*16));
        const uint32_t b2 = bcb +
            SWZ128((uint32_t)((wn*24 + 16 + rowb2)*128 + ki*32 + kh2*16));
        LDSM_X4(Bh4[ks][0], Bh4[ks][1], Bh4[ks][2], Bh4[ks][3], b4);
        LDSM_X2(Bh2[ks][0], Bh2[ks][1], b2);
    }

    __nv_bfloat16* obh = (LAYER == 0) ? d_h1hi : d_h2hi;
    __nv_bfloat16* obl = (LAYER == 0) ? d_h1lo : d_h2lo;
    const unsigned LB = (unsigned)(LAYER * 512);

    for (int s_ = 0; s_ < 512; s_++) {
        // prefetch x-projections (independent of peers -> issue before poll)
        const int t_in = (dir == 0) ? s_ : (511 - s_);
        float4 xr4, xz4, xn4;
        if (LAYER == 0) {
            const int tok = __ldg(inputs + bg*512 + t_in);
            const float* pt = d_ptab + ((size_t)dir*65 + tok)*768 + j0 + ju;
            xr4 = __ldg((const float4*)(pt));
            xz4 = __ldg((const float4*)(pt + 256));
            xn4 = __ldg((const float4*)(pt + 512));
        } else {
            const float* xp = d_xp1 + ((size_t)dir*131072 + (size_t)t_in*256 + bg)*768 + j0 + ju;
            xr4 = __ldg((const float4*)(xp));
            xz4 = __ldg((const float4*)(xp + 256));
            xn4 = __ldg((const float4*)(xp + 512));
        }

        if (s_ > 0) {
            poll_group(gid, LB + (unsigned)s_, lane);
            // read peers' h from the OUTPUT buffer at t_prev (row stride 512)
            const int t_prev = (dir == 0) ? (s_ - 1) : (512 - s_);
            const __nv_bfloat16* ghi = obh + ((size_t)t_prev*256 + b0)*512 + (size_t)dir*256;
            const __nv_bfloat16* glo = obl + ((size_t)t_prev*256 + b0)*512 + (size_t)dir*256;
            #pragma unroll
            for (int v = 0; v < 4; v++) {
                int vv = tid + v*256;          // 0..1023
                int r   = vv >> 5;             // 0..31 (batch row)
                int ks16 = vv & 31;            // 16B segment (8 bf16)
                uint32_t dst = SWZ128((uint32_t)((ks16 >> 3)*4096 + r*128 + (ks16 & 7)*16));
                size_t gofs = (size_t)r*512 + (size_t)ks16*8;
                cp16(base + 98304u  + dst, ghi + gofs);
                cp16(base + 114688u + dst, glo + gofs);
            }
            CP_COMMIT(); CP_WAIT(0);
            __syncthreads();
        }

        // ---- MMA: G = h @ Wslice^T, 3-pass split (W-hi from registers) ----
        float c[3][4];
        #pragma unroll
        for (int fn = 0; fn < 3; fn++)
            #pragma unroll
            for (int q = 0; q < 4; q++) c[fn][q] = 0.f;

        #pragma unroll
        for (int ks = 0; ks < 16; ks++) {
            const int ck = ks >> 2, ki = ks & 3;
            const uint32_t ain = base + 98304u + (uint32_t)ck*4096u +
                SWZ128((uint32_t)((wm*16 + lrow)*128 + ki*32 + kseg*16));
            uint32_t ah[4], al[4];
            LDSM_X4(ah[0], ah[1], ah[2], ah[3], ain);
            LDSM_X4(al[0], al[1], al[2], al[3], ain + 16384u);
            const uint32_t bcb = base + 49152u + (uint32_t)ck*12288u;
            const uint32_t b4l = bcb +
                SWZ128((uint32_t)((wn*24 + nrx4)*128 + ki*32 + ksx4*16));
            const uint32_t b2l = bcb +
                SWZ128((uint32_t)((wn*24 + 16 + rowb2)*128 + ki*32 + kh2*16));
            uint32_t bl[3][2];
            LDSM_X4(bl[0][0], bl[0][1], bl[1][0], bl[1][1], b4l);
            LDSM_X2(bl[2][0], bl[2][1], b2l);
            uint32_t bh0[2] = {Bh4[ks][0], Bh4[ks][1]};
            uint32_t bh1[2] = {Bh4[ks][2], Bh4[ks][3]};
            uint32_t bh2v[2] = {Bh2[ks][0], Bh2[ks][1]};
            mma16816(c[0], ah, bh0);
            mma16816(c[1], ah, bh1);
            mma16816(c[2], ah, bh2v);
            #pragma unroll
            for (int fn = 0; fn < 3; fn++)
                mma16816(c[fn], ah, bl[fn]);
            mma16816(c[0], al, bh0);
            mma16816(c[1], al, bh1);
            mma16816(c[2], al, bh2v);
        }

        // write G to smem
        {
            const int l4 = lane >> 2, l2 = (lane & 3)*2;
            #pragma unroll
            for (int fn = 0; fn < 3; fn++) {
                const int col = wn*24 + fn*8 + l2;
                *(float2*)&Gs[(wm*16 + l4)*100 + col]     = make_float2(c[fn][0], c[fn][1]);
                *(float2*)&Gs[(wm*16 + l4 + 8)*100 + col] = make_float2(c[fn][2], c[fn][3]);
            }
        }
        __syncthreads();

        // ---- nonlinearity + h update ----
        {
            float4 gr = *(const float4*)&Gs[bb*100 + ju];
            float4 gz = *(const float4*)&Gs[bb*100 + 32 + ju];
            float4 gn = *(const float4*)&Gs[bb*100 + 64 + ju];
            float4 hp = *(const float4*)&Hprev[bb*36 + ju];
            float hn[4];
            const float* xr = &xr4.x;
            const float* xz = &xz4.x;
            const float* xn = &xn4.x;
            const float* grp = &gr.x;
            const float* gzp = &gz.x;
            const float* gnp = &gn.x;
            const float* hpp = &hp.x;
            #pragma unroll
            for (int i = 0; i < 4; i++) {
                float r = fsig(xr[i] + grp[i] + bhh_s[     ju + i]);
                float z = fsig(xz[i] + gzp[i] + bhh_s[32 + ju + i]);
                float n = ftanh(xn[i] + r*(gnp[i] + bhh_s[64 + ju + i]));
                hn[i] = (1.f - z)*n + z*hpp[i];
            }
            float4 hv = make_float4(hn[0], hn[1], hn[2], hn[3]);
            *(float4*)&Hprev[bb*36 + ju] = hv;
            uint2 hhi, hlo;
            split4(hv, hhi, hlo);
            size_t oo = ((size_t)t_in*256 + bg)*512 + (size_t)dir*256 + j0 + ju;
            asm volatile("st.global.cg.v2.u32 [%0], {%1,%2};" :: "l"(obh + oo), "r"(hhi.x), "r"(hhi.y));
            asm volatile("st.global.cg.v2.u32 [%0], {%1,%2};" :: "l"(obl + oo), "r"(hlo.x), "r"(hlo.y));
        }
        if (s_ != 511) {
            __threadfence();
            __syncthreads();
            if (tid == 0) {
                asm volatile("st.global.release.gpu.u32 [%0], %1;"
                    :: "l"(d_flags + (gid*8 + us)*32), "r"(LB + (unsigned)(s_ + 1)));
            }
        }
    }
}

// ---------------- split-bf16 warp-MMA GEMM (mma.sync m16n8k16 bf16) ----------------
// MODE 0: xp1 = h1 @ wih1^T + bias.  grid (1024 mtiles, 6 ntiles, 2 dirs)
// MODE 1: fc1 partials per t.        grid (2 mtiles, 1, 512 t)
#define MMA_DSMEM (2*65536 + 1024)

template<int MODE>
__global__ void __launch_bounds__(256) mma_gemm_kernel(
    const __nv_bfloat16* __restrict__ Ah, const __nv_bfloat16* __restrict__ Al,
    const __nv_bfloat16* __restrict__ Bh, const __nv_bfloat16* __restrict__ Bl,
    const float* __restrict__ bias, float* __restrict__ outp) {
    extern __shared__ char dsm_raw[];
    const uint32_t raw  = smem_to_u32(dsm_raw);
    const uint32_t base = (raw + 1023u) & ~1023u;

    const int tid  = threadIdx.x;
    const int lane = tid & 31;
    const int wid  = tid >> 5;
    const int wm   = wid >> 2;
    const int wn   = wid & 3;

    size_t arow0, brow0, bstride, bk0;
    if (MODE == 0) {
        arow0 = (size_t)blockIdx.x * 128;
        brow0 = (size_t)blockIdx.z * 768 + (size_t)blockIdx.y * 128;
        bstride = 512; bk0 = 0;
    } else {
        arow0 = (size_t)blockIdx.z * 256 + (size_t)blockIdx.x * 128;
        brow0 = 0;
        bstride = 262144; bk0 = (size_t)blockIdx.z * 512;
    }

    float c[4][4][4];
    #pragma unroll
    for (int fm = 0; fm < 4; fm++)
    #pragma unroll
    for (int fn = 0; fn < 4; fn++)
    #pragma unroll
    for (int q = 0; q < 4; q++) c[fm][fn][q] = 0.f;

    auto issue = [&](int kc, int buf) {
        const uint32_t sbb = base + (uint32_t)buf*65536u;
        #pragma unroll
        for (int v = 0; v < 4; v++) {
            int vv = tid + v*256;
            int r = vv >> 3, seg = vv & 7;
            uint32_t sw = SWZ128((uint32_t)(r*128 + seg*16));
            size_t k  = (size_t)kc*64 + (size_t)seg*8;
            size_t ga = (arow0 + r)*512 + k;
            size_t gb = (brow0 + r)*bstride + bk0 + k;
            cp16(sbb +          sw, Ah + ga);
            cp16(sbb + 16384u + sw, Al + ga);
            cp16(sbb + 32768u + sw, Bh + gb);
            cp16(sbb + 49152u + sw, Bl + gb);
        }
    };

    issue(0, 0); CP_COMMIT();

    for (int kc = 0; kc < 8; kc++) {
        if (kc < 7) {
            issue(kc + 1, (kc + 1) & 1); CP_COMMIT();
            CP_WAIT(1);
        } else {
            CP_WAIT(0);
        }
        __syncthreads();

        const uint32_t sbb = base + (uint32_t)(kc & 1)*65536u;
        const int lrow = lane & 15, kseg = lane >> 4;
        const int g = lane >> 3, lr = lane & 7;
        const int nrow = ((g >> 1) & 1)*8 + lr;
        const int ks2 = g & 1;

        #pragma unroll
        for (int ki = 0; ki < 4; ki++) {
            uint32_t ahf[4][4], alf[4][4];
            #pragma unroll
            for (int fm = 0; fm < 4; fm++) {
                uint32_t off = SWZ128((uint32_t)((wm*64 + fm*16 + lrow)*128 + ki*32 + kseg*16));
                LDSM_X4(ahf[fm][0], ahf[fm][1], ahf[fm][2], ahf[fm][3], sbb + off);
                LDSM_X4(alf[fm][0], alf[fm][1], alf[fm][2], alf[fm][3], sbb + 16384u + off);
            }
            uint32_t bhf[4][2], blf[4][2];
            #pragma unroll
            for (int fp = 0; fp < 2; fp++) {
                uint32_t off = SWZ128((uint32_t)((wn*32 + fp*16 + nrow)*128 + ki*32 + ks2*16));
                LDSM_X4(bhf[fp*2][0], bhf[fp*2][1], bhf[fp*2+1][0], bhf[fp*2+1][1], sbb + 32768u + off);
                LDSM_X4(blf[fp*2][0], blf[fp*2][1], blf[fp*2+1][0], blf[fp*2+1][1], sbb + 49152u + off);
            }
            #pragma unroll
            for (int fm = 0; fm < 4; fm++)
            #pragma unroll
            for (int fn = 0; fn < 4; fn++) {
                mma16816(c[fm][fn], ahf[fm], bhf[fn]);
                mma16816(c[fm][fn], ahf[fm], blf[fn]);
                mma16816(c[fm][fn], alf[fm], bhf[fn]);
            }
        }
        __syncthreads();
    }

    const int l4 = lane >> 2;
    const int l2 = (lane & 3)*2;
    #pragma unroll
    for (int fm = 0; fm < 4; fm++) {
        const int mr0 = wm*64 + fm*16 + l4;
        #pragma unroll
        for (int fn = 0; fn < 4; fn++) {
            const int col = wn*32 + fn*8 + l2;
            if (MODE == 0) {
                const int gcol = blockIdx.y*128 + col;
                float2 bv = *(const float2*)(bias + blockIdx.z*768 + gcol);
                size_t m0 = (size_t)blockIdx.z*131072 + (size_t)blockIdx.x*128 + mr0;
                *(float2*)(outp + m0*768 + gcol)       = make_float2(c[fm][fn][0] + bv.x, c[fm][fn][1] + bv.y);
                *(float2*)(outp + (m0 + 8)*768 + gcol) = make_float2(c[fm][fn][2] + bv.x, c[fm][fn][3] + bv.y);
            } else {
                size_t m0 = (size_t)blockIdx.z*256 + (size_t)blockIdx.x*128 + mr0;
                *(float2*)(outp + m0*128 + col)       = make_float2(c[fm][fn][0], c[fm][fn][1]);
                *(float2*)(outp + (m0 + 8)*128 + col) = make_float2(c[fm][fn][2], c[fm][fn][3]);
            }
        }
    }
}

// ---------------- final reduce + MLP head ----------------
__global__ void __launch_bounds__(128) fc_reduce_kernel(
    const float* __restrict__ b1, const float* __restrict__ W2,
    const float* __restrict__ b2, float* __restrict__ out) {
    const int b = blockIdx.x;
    const int o = threadIdx.x;
    const float* p = d_fc1p + (size_t)b*128 + o;
    float s0 = 0.f, s1 = 0.f, s2 = 0.f, s3 = 0.f;
    #pragma unroll 4
    for (int t = 0; t < 512; t += 4) {
        s0 += p[(size_t)(t+0)*32768];
        s1 += p[(size_t)(t+1)*32768];
        s2 += p[(size_t)(t+2)*32768];
        s3 += p[(size_t)(t+3)*32768];
    }
    float s = b1[o] + ((s0 + s1) + (s2 + s3));
    float v = s > 0.f ? s : 0.01f*s;
    float c = v * __ldg(W2 + o);
    __shared__ float red[128];
    red[o] = c;
    __syncthreads();
    for (int st = 64; st > 0; st >>= 1) {
        if (o < st) red[o] += red[o + st];
        __syncthreads();
    }
    if (o == 0) out[b] = 1.f/(1.f + expf(-(red[0] + b2[0])));
}

// ---------------- launch ----------------
extern "C" void kernel_launch(void* const* d_in, const int* in_sizes, int n_in,
                              void* d_out, int out_size) {
    const int*   inputs = (const int*)  d_in[0];
    const float* emb    = (const float*)d_in[1];
    const float* wih0   = (const float*)d_in[2];
    const float* whh0   = (const float*)d_in[3];
    const float* bih0   = (const float*)d_in[4];
    const float* bhh0   = (const float*)d_in[5];
    const float* wih1   = (const float*)d_in[6];
    const float* whh1   = (const float*)d_in[7];
    const float* bih1   = (const float*)d_in[8];
    const float* bhh1   = (const float*)d_in[9];
    const float* W1     = (const float*)d_in[10];
    const float* b1     = (const float*)d_in[11];
    const float* W2     = (const float*)d_in[12];
    const float* b2     = (const float*)d_in[13];
    float* out = (float*)d_out;

    cudaFuncSetAttribute((const void*)rec_mma_kernel<0>,
                         cudaFuncAttributeMaxDynamicSharedMemorySize, RECM_SMEM);
    cudaFuncSetAttribute((const void*)rec_mma_kernel<1>,
                         cudaFuncAttributeMaxDynamicSharedMemorySize, RECM_SMEM);
    cudaFuncSetAttribute((const void*)mma_gemm_kernel<0>,
                         cudaFuncAttributeMaxDynamicSharedMemorySize, MMA_DSMEM);
    cudaFuncSetAttribute((const void*)mma_gemm_kernel<1>,
                         cudaFuncAttributeMaxDynamicSharedMemorySize, MMA_DSMEM);

    __nv_bfloat16 *h1hi, *h1lo, *h2hi, *h2lo, *wihhi, *wihlo, *W1hi, *W1lo;
    cudaGetSymbolAddress((void**)&h1hi, d_h1hi);
    cudaGetSymbolAddress((void**)&h1lo, d_h1lo);
    cudaGetSymbolAddress((void**)&h2hi, d_h2hi);
    cudaGetSymbolAddress((void**)&h2lo, d_h2lo);
    cudaGetSymbolAddress((void**)&wihhi, d_wihhi);
    cudaGetSymbolAddress((void**)&wihlo, d_wihlo);
    cudaGetSymbolAddress((void**)&W1hi, d_W1hi);
    cudaGetSymbolAddress((void**)&W1lo, d_W1lo);
    float *xp1p, *fc1p;
    cudaGetSymbolAddress((void**)&xp1p, d_xp1);
    cudaGetSymbolAddress((void**)&fc1p, d_fc1p);

    proj0_kernel<<<130, 256>>>(emb, wih0, bih0);
    split_kernel<<<768, 256>>>(wih1, wihhi, wihlo, 196608);
    split_kernel<<<4096, 256>>>(W1, W1hi, W1lo, 8388608);
    reset_bar_kernel<<<16, 256>>>();
    rec_mma_kernel<0><<<128, 256, RECM_SMEM>>>(inputs, whh0, bhh0);
    mma_gemm_kernel<0><<<dim3(1024, 6, 2), 256, MMA_DSMEM>>>(h1hi, h1lo, wihhi, wihlo, bih1, xp1p);
    rec_mma_kernel<1><<<128, 256, RECM_SMEM>>>(inputs, whh1, bhh1);
    mma_gemm_kernel<1><<<dim3(2, 1, 512), 256, MMA_DSMEM>>>(h2hi, h2lo, W1hi, W1lo, nullptr, fc1p);
    fc_reduce_kernel<<<256, 128>>>(b1, W2, b2, out);
}

// round 14
// speedup vs baseline: 1.1357x; 1.0828x over previous
#include <cuda_runtime.h>
#include <cuda_bf16.h>
#include <math.h>
#include <stddef.h>
#include <stdint.h>

// B=256, T=512, V=64(65 rows), E=128, H=256, 3H=768, D=2

// ---------------- PTX helpers (baseline ISA only: sm_80-era, safe on sm_103) ----------------
__device__ __forceinline__ uint32_t smem_to_u32(const void* p) {
    uint32_t a;
    asm("{ .reg .u64 t; cvta.to.shared.u64 t, %1; cvt.u32.u64 %0, t; }" : "=r"(a) : "l"(p));
    return a;
}
__device__ __forceinline__ void cp16(uint32_t s, const void* g) {
    asm volatile("cp.async.cg.shared.global [%0], [%1], 16;" :: "r"(s), "l"(g) : "memory");
}
#define CP_COMMIT() asm volatile("cp.async.commit_group;" ::: "memory")
#define CP_WAIT(n)  asm volatile("cp.async.wait_group %0;" :: "n"(n) : "memory")
#define LDSM_X4(r0, r1, r2, r3, addr) \
    asm volatile("ldmatrix.sync.aligned.m8n8.x4.shared.b16 {%0,%1,%2,%3}, [%4];" \
        : "=r"(r0), "=r"(r1), "=r"(r2), "=r"(r3) : "r"(addr))
#define LDSM_X2(r0, r1, addr) \
    asm volatile("ldmatrix.sync.aligned.m8n8.x2.shared.b16 {%0,%1}, [%2];" \
        : "=r"(r0), "=r"(r1) : "r"(addr))

__device__ __forceinline__ void mma16816(float* c, const uint32_t* a, const uint32_t* b) {
    asm volatile(
        "mma.sync.aligned.m16n8k16.row.col.f32.bf16.bf16.f32 "
        "{%0,%1,%2,%3}, {%4,%5,%6,%7}, {%8,%9}, {%0,%1,%2,%3};"
        : "+f"(c[0]), "+f"(c[1]), "+f"(c[2]), "+f"(c[3])
        : "r"(a[0]), "r"(a[1]), "r"(a[2]), "r"(a[3]), "r"(b[0]), "r"(b[1]));
}

#define SWZ128(b) ((b) ^ (((b) >> 3) & 0x70))

// pack 4 floats -> hi/lo bf16 pairs (8 bytes each)
__device__ __forceinline__ void split4(float4 v, uint2& hi, uint2& lo) {
    __nv_bfloat16 a0 = __float2bfloat16(v.x), a1 = __float2bfloat16(v.y);
    __nv_bfloat16 a2 = __float2bfloat16(v.z), a3 = __float2bfloat16(v.w);
    __nv_bfloat16 l0 = __float2bfloat16(v.x - __bfloat162float(a0));
    __nv_bfloat16 l1 = __float2bfloat16(v.y - __bfloat162float(a1));
    __nv_bfloat16 l2 = __float2bfloat16(v.z - __bfloat162float(a2));
    __nv_bfloat16 l3 = __float2bfloat16(v.w - __bfloat162float(a3));
    __nv_bfloat162 h01 = __halves2bfloat162(a0, a1), h23 = __halves2bfloat162(a2, a3);
    __nv_bfloat162 m01 = __halves2bfloat162(l0, l1), m23 = __halves2bfloat162(l2, l3);
    hi.x = *(uint32_t*)&h01; hi.y = *(uint32_t*)&h23;
    lo.x = *(uint32_t*)&m01; lo.y = *(uint32_t*)&m23;
}

__device__ __forceinline__ float tanh_ap(float x) {
    float y;
    asm("tanh.approx.f32 %0, %1;" : "=f"(y) : "f"(x));
    return y;
}
// sigmoid via HW tanh: sig(x) = 0.5*tanh(0.5x) + 0.5
__device__ __forceinline__ float fsig(float x) {
    return fmaf(tanh_ap(0.5f*x), 0.5f, 0.5f);
}
// accurate-ish tanh for the n gate (additive path)
__device__ __forceinline__ float ftanh(float x) {
    return __fdividef(2.f, 1.f + __expf(-2.f*x)) - 1.f;
}

// ---------------- static scratch ----------------
__device__ float d_ptab [2*65*768];
__device__ float d_xp1  [2*512*256*768];
__device__ float d_fc1p [512*256*128];
__device__ __nv_bfloat16 d_h1hi[67108864], d_h1lo[67108864];
__device__ __nv_bfloat16 d_h2hi[67108864], d_h2lo[67108864];
__device__ __nv_bfloat16 d_wihhi[786432], d_wihlo[786432];
__device__ __nv_bfloat16 d_W1hi[33554432], d_W1lo[33554432];
__device__ unsigned d_flags[4096];   // [16 groups][8 slots][32 pad]

__global__ void reset_bar_kernel() {
    d_flags[blockIdx.x*256 + threadIdx.x] = 0u;
}

// consumer-side poll: 8 lanes poll the 8 peer flags of the group
__device__ __forceinline__ void poll_group(int gid, unsigned target, int lane) {
    if (lane < 8) {
        const unsigned* f = d_flags + (gid*8 + lane)*32;
        unsigned v;
        while (true) {
            asm volatile("ld.global.acquire.gpu.u32 %0, [%1];" : "=r"(v) : "l"(f));
            if (v >= target) break;
            __nanosleep(20);
        }
    }
    __syncwarp();
}

// ---------------- L0 proj table ----------------
__global__ void __launch_bounds__(256) proj0_kernel(const float* __restrict__ emb,
                                                    const float* __restrict__ wih,
                                                    const float* __restrict__ bih) {
    const int d = blockIdx.x / 65;
    const int v = blockIdx.x % 65;
    __shared__ float es[128];
    if (threadIdx.x < 128) es[threadIdx.x] = emb[v*128 + threadIdx.x];
    __syncthreads();
    for (int g = threadIdx.x; g < 768; g += 256) {
        const float* w = wih + ((size_t)d*768 + g)*128;
        float s = bih[d*768 + g];
        #pragma unroll 4
        for (int e = 0; e < 128; e++) s += es[e]*__ldg(w + e);
        d_ptab[((size_t)d*65 + v)*768 + g] = s;
    }
}

// ---------------- fp32 -> bf16 hi/lo split (weights only) ----------------
__global__ void __launch_bounds__(256) split_kernel(const float* __restrict__ x,
        __nv_bfloat16* __restrict__ hi, __nv_bfloat16* __restrict__ lo, size_t n4) {
    size_t i = (size_t)blockIdx.x*256 + threadIdx.x;
    size_t stride = (size_t)gridDim.x*256;
    for (; i < n4; i += stride) {
        float4 v = __ldg((const float4*)x + i);
        uint2 h, l;
        split4(v, h, l);
        ((uint2*)hi)[i] = h;
        ((uint2*)lo)[i] = l;
    }
}

// ---------------- MMA recurrence (both layers) ----------------
// 128 CTAs = dir(2) x batch-slice(8 x 32 rows) x unit-slice(8 x 32 units)
// Per step: G[32 x 96] = h[32 x 256] @ Wslice[96 x 256]^T via split-bf16 3-pass mma.
// W-hi fragments hoisted into registers (96/thread). Exchange cp.async split into
// two commit groups so the first MMA half overlaps the second half's fetch.
// SMEM layout (1024-aligned base):
//   WHI  @ 0      : 49152 (read during init preload only)
//   WLO  @ 49152  : 49152
//   HHI  @ 98304  : 16384
//   HLO  @ 114688 : 16384
//   G    @ 131072 : 32 x 100 floats = 12800
//   HPREV@ 143872 : 32 x 36 floats  = 4608
#define RECM_SMEM (148480 + 1024)

template<int LAYER>
__global__ void __launch_bounds__(256, 1) rec_mma_kernel(
    const int* __restrict__ inputs,
    const float* __restrict__ w_hh,
    const float* __restrict__ b_hh) {
    extern __shared__ char sm_raw[];
    __shared__ float bhh_s[96];
    const uint32_t raw  = smem_to_u32(sm_raw);
    const uint32_t base = (raw + 1023u) & ~1023u;
    char* sb = sm_raw + (base - raw);
    float* Gs    = (float*)(sb + 131072);
    float* Hprev = (float*)(sb + 143872);

    const int bid = blockIdx.x;
    const int dir = bid >> 6;
    const int rem = bid & 63;
    const int bs  = rem >> 3;
    const int us  = rem & 7;
    const int b0  = bs * 32;
    const int j0  = us * 32;
    const int gid = dir*8 + bs;
    const int tid = threadIdx.x;
    const int lane = tid & 31;
    const int wid  = tid >> 5;

    // ---- one-time: W_hh slice -> bf16 hi/lo swizzled smem (gate-interleaved rows) ----
    {
        const int k0 = (tid & 7) * 32;
        #pragma unroll
        for (int rr = 0; rr < 3; rr++) {
            const int lr = rr*32 + (tid >> 3);
            const int g  = lr >> 5;
            const float* src = w_hh + ((size_t)dir*768 + g*256 + j0 + (lr & 31))*256 + k0;
            const uint32_t cb = (uint32_t)(k0 >> 6)*12288u + (uint32_t)lr*128u + (uint32_t)(k0 & 63)*2u;
            #pragma unroll
            for (int q = 0; q < 8; q++) {
                float4 v = __ldg((const float4*)src + q);
                uint2 h, l;
                split4(v, h, l);
                uint32_t off = SWZ128(cb + q*8);
                *(uint2*)(sb + off)          = h;
                *(uint2*)(sb + 49152u + off) = l;
            }
        }
    }
    if (tid < 96) bhh_s[tid] = b_hh[dir*768 + (tid>>5)*256 + j0 + (tid & 31)];
    // zero h tiles + hprev
    for (int i = tid; i < 2048; i += 256)
        ((uint4*)(sb + 98304))[i] = make_uint4(0,0,0,0);
    for (int i = tid; i < 1152; i += 256)
        Hprev[i] = 0.f;
    __syncthreads();

    // per-thread nonlinearity mapping
    const int bb = tid >> 3;
    const int ju = (tid & 7) * 4;
    const int bg = b0 + bb;

    // MMA lane mappings
    const int wm = wid >> 2, wn = wid & 3;
    const int lrow = lane & 15, kseg = lane >> 4;
    const int g8 = lane >> 3, lr8 = lane & 7;
    const int nrx4 = ((g8 >> 1) & 1)*8 + lr8;
    const int ksx4 = g8 & 1;
    const int lx = lane & 15;
    const int rowb2 = lx & 7, kh2 = (lx >> 3) & 1;

    // ---- hoist W-hi B-fragments into registers (step-invariant, 96 regs) ----
    uint32_t Bh4[16][4], Bh2[16][2];
    #pragma unroll
    for (int ks = 0; ks < 16; ks++) {
        const int ck = ks >> 2, ki = ks & 3;
        const uint32_t bcb = base + (uint32_t)ck*12288u;
        const uint32_t b4 = bcb +
            SWZ128((uint32_t)((wn*24 + nrx4)*128 + ki*32 + ksx4*16));
        const uint32_t b2 = bcb +
            SWZ128((uint32_t)((wn*24 + 16 + rowb2)*128 + ki*32 + kh2*16));
        LDSM_X4(Bh4[ks][0], Bh4[ks][1], Bh4[ks][2], Bh4[ks][3], b4);
        LDSM_X2(Bh2[ks][0], Bh2[ks][1], b2);
    }

    __nv_bfloat16* obh = (LAYER == 0) ? d_h1hi : d_h2hi;
    __nv_bfloat16* obl = (LAYER == 0) ? d_h1lo : d_h2lo;
    const unsigned LB = (unsigned)(LAYER * 512);

    for (int s_ = 0; s_ < 512; s_++) {
        // prefetch x-projections (independent of peers -> issue before poll)
        const int t_in = (dir == 0) ? s_ : (511 - s_);
        float4 xr4, xz4, xn4;
        if (LAYER == 0) {
            const int tok = __ldg(inputs + bg*512 + t_in);
            const float* pt = d_ptab + ((size_t)dir*65 + tok)*768 + j0 + ju;
            xr4 = __ldg((const float4*)(pt));
            xz4 = __ldg((const float4*)(pt + 256));
            xn4 = __ldg((const float4*)(pt + 512));
        } else {
            const float* xp = d_xp1 + ((size_t)dir*131072 + (size_t)t_in*256 + bg)*768 + j0 + ju;
            xr4 = __ldg((const float4*)(xp));
            xz4 = __ldg((const float4*)(xp + 256));
            xn4 = __ldg((const float4*)(xp + 512));
        }

        if (s_ > 0) {
            poll_group(gid, LB + (unsigned)s_, lane);
            // read peers' h from the OUTPUT buffer at t_prev (row stride 512)
            // split into two commit groups: chunks {0,1} then {2,3}
            const int t_prev = (dir == 0) ? (s_ - 1) : (512 - s_);
            const __nv_bfloat16* ghi = obh + ((size_t)t_prev*256 + b0)*512 + (size_t)dir*256;
            const __nv_bfloat16* glo = obl + ((size_t)t_prev*256 + b0)*512 + (size_t)dir*256;
            const int r   = tid >> 3;            // 0..31 (batch row)
            const int sg  = tid & 7;             // 16B segment within 64-col chunk
            #pragma unroll
            for (int ck = 0; ck < 4; ck++) {
                uint32_t dst = SWZ128((uint32_t)(ck*4096 + r*128 + sg*16));
                size_t gofs = (size_t)r*512 + (size_t)ck*64 + (size_t)sg*8;
                cp16(base + 98304u  + dst, ghi + gofs);
                cp16(base + 114688u + dst, glo + gofs);
                if (ck == 1) CP_COMMIT();
            }
            CP_COMMIT();
        }

        // ---- MMA: G = h @ Wslice^T, 3-pass split (W-hi from registers) ----
        float c[3][4];
        #pragma unroll
        for (int fn = 0; fn < 3; fn++)
            #pragma unroll
            for (int q = 0; q < 4; q++) c[fn][q] = 0.f;

        #pragma unroll
        for (int half = 0; half < 2; half++) {
            if (s_ > 0) { if (half == 0) { CP_WAIT(1); } else { CP_WAIT(0); } }
            __syncthreads();
            #pragma unroll
            for (int ks8 = 0; ks8 < 8; ks8++) {
                const int ks = half*8 + ks8;
                const int ck = ks >> 2, ki = ks & 3;
                const uint32_t ain = base + 98304u + (uint32_t)ck*4096u +
                    SWZ128((uint32_t)((wm*16 + lrow)*128 + ki*32 + kseg*16));
                uint32_t ah[4], al[4];
                LDSM_X4(ah[0], ah[1], ah[2], ah[3], ain);
                LDSM_X4(al[0], al[1], al[2], al[3], ain + 16384u);
                const uint32_t bcb = base + 49152u + (uint32_t)ck*12288u;
                const uint32_t b4l = bcb +
                    SWZ128((uint32_t)((wn*24 + nrx4)*128 + ki*32 + ksx4*16));
                const uint32_t b2l = bcb +
                    SWZ128((uint32_t)((wn*24 + 16 + rowb2)*128 + ki*32 + kh2*16));
                uint32_t bl[3][2];
                LDSM_X4(bl[0][0], bl[0][1], bl[1][0], bl[1][1], b4l);
                LDSM_X2(bl[2][0], bl[2][1], b2l);
                uint32_t bh0[2] = {Bh4[ks][0], Bh4[ks][1]};
                uint32_t bh1[2] = {Bh4[ks][2], Bh4[ks][3]};
                uint32_t bh2v[2] = {Bh2[ks][0], Bh2[ks][1]};
                mma16816(c[0], ah, bh0);
                mma16816(c[1], ah, bh1);
                mma16816(c[2], ah, bh2v);
                #pragma unroll
                for (int fn = 0; fn < 3; fn++)
                    mma16816(c[fn], ah, bl[fn]);
                mma16816(c[0], al, bh0);
                mma16816(c[1], al, bh1);
                mma16816(c[2], al, bh2v);
            }
        }

        // write G to smem
        {
            const int l4 = lane >> 2, l2 = (lane & 3)*2;
            #pragma unroll
            for (int fn = 0; fn < 3; fn++) {
                const int col = wn*24 + fn*8 + l2;
                *(float2*)&Gs[(wm*16 + l4)*100 + col]     = make_float2(c[fn][0], c[fn][1]);
                *(float2*)&Gs[(wm*16 + l4 + 8)*100 + col] = make_float2(c[fn][2], c[fn][3]);
            }
        }
        __syncthreads();

        // ---- nonlinearity + h update ----
        {
            float4 gr = *(const float4*)&Gs[bb*100 + ju];
            float4 gz = *(const float4*)&Gs[bb*100 + 32 + ju];
            float4 gn = *(const float4*)&Gs[bb*100 + 64 + ju];
            float4 hp = *(const float4*)&Hprev[bb*36 + ju];
            float hn[4];
            const float* xr = &xr4.x;
            const float* xz = &xz4.x;
            const float* xn = &xn4.x;
            const float* grp = &gr.x;
            const float* gzp = &gz.x;
            const float* gnp = &gn.x;
            const float* hpp = &hp.x;
            #pragma unroll
            for (int i = 0; i < 4; i++) {
                float r = fsig(xr[i] + grp[i] + bhh_s[     ju + i]);
                float z = fsig(xz[i] + gzp[i] + bhh_s[32 + ju + i]);
                float n = ftanh(xn[i] + r*(gnp[i] + bhh_s[64 + ju + i]));
                hn[i] = (1.f - z)*n + z*hpp[i];
            }
            float4 hv = make_float4(hn[0], hn[1], hn[2], hn[3]);
            *(float4*)&Hprev[bb*36 + ju] = hv;
            uint2 hhi, hlo;
            split4(hv, hhi, hlo);
            size_t oo = ((size_t)t_in*256 + bg)*512 + (size_t)dir*256 + j0 + ju;
            asm volatile("st.global.cg.v2.u32 [%0], {%1,%2};" :: "l"(obh + oo), "r"(hhi.x), "r"(hhi.y));
            asm volatile("st.global.cg.v2.u32 [%0], {%1,%2};" :: "l"(obl + oo), "r"(hlo.x), "r"(hlo.y));
        }
        if (s_ != 511) {
            __syncthreads();
            if (tid == 0) {
                asm volatile("st.global.release.gpu.u32 [%0], %1;"
                    :: "l"(d_flags + (gid*8 + us)*32), "r"(LB + (unsigned)(s_ + 1)));
            }
        }
    }
}

// ---------------- split-bf16 warp-MMA GEMM (mma.sync m16n8k16 bf16) ----------------
// MODE 0: xp1 = h1 @ wih1^T + bias.  grid (1024 mtiles, 6 ntiles, 2 dirs)
// MODE 1: fc1 partials per t.        grid (2 mtiles, 1, 512 t)
#define MMA_DSMEM (2*65536 + 1024)

template<int MODE>
__global__ void __launch_bounds__(256) mma_gemm_kernel(
    const __nv_bfloat16* __restrict__ Ah, const __nv_bfloat16* __restrict__ Al,
    const __nv_bfloat16* __restrict__ Bh, const __nv_bfloat16* __restrict__ Bl,
    const float* __restrict__ bias, float* __restrict__ outp) {
    extern __shared__ char dsm_raw[];
    const uint32_t raw  = smem_to_u32(dsm_raw);
    const uint32_t base = (raw + 1023u) & ~1023u;

    const int tid  = threadIdx.x;
    const int lane = tid & 31;
    const int wid  = tid >> 5;
    const int wm   = wid >> 2;
    const int wn   = wid & 3;

    size_t arow0, brow0, bstride, bk0;
    if (MODE == 0) {
        arow0 = (size_t)blockIdx.x * 128;
        brow0 = (size_t)blockIdx.z * 768 + (size_t)blockIdx.y * 128;
        bstride = 512; bk0 = 0;
    } else {
        arow0 = (size_t)blockIdx.z * 256 + (size_t)blockIdx.x * 128;
        brow0 = 0;
        bstride = 262144; bk0 = (size_t)blockIdx.z * 512;
    }

    float c[4][4][4];
    #pragma unroll
    for (int fm = 0; fm < 4; fm++)
    #pragma unroll
    for (int fn = 0; fn < 4; fn++)
    #pragma unroll
    for (int q = 0; q < 4; q++) c[fm][fn][q] = 0.f;

    auto issue = [&](int kc, int buf) {
        const uint32_t sbb = base + (uint32_t)buf*65536u;
        #pragma unroll
        for (int v = 0; v < 4; v++) {
            int vv = tid + v*256;
            int r = vv >> 3, seg = vv & 7;
            uint32_t sw = SWZ128((uint32_t)(r*128 + seg*16));
            size_t k  = (size_t)kc*64 + (size_t)seg*8;
            size_t ga = (arow0 + r)*512 + k;
            size_t gb = (brow0 + r)*bstride + bk0 + k;
            cp16(sbb +          sw, Ah + ga);
            cp16(sbb + 16384u + sw, Al + ga);
            cp16(sbb + 32768u + sw, Bh + gb);
            cp16(sbb + 49152u + sw, Bl + gb);
        }
    };

    issue(0, 0); CP_COMMIT();

    for (int kc = 0; kc < 8; kc++) {
        if (kc < 7) {
            issue(kc + 1, (kc + 1) & 1); CP_COMMIT();
            CP_WAIT(1);
        } else {
            CP_WAIT(0);
        }
        __syncthreads();

        const uint32_t sbb = base + (uint32_t)(kc & 1)*65536u;
        const int lrow = lane & 15, kseg = lane >> 4;
        const int g = lane >> 3, lr = lane & 7;
        const int nrow = ((g >> 1) & 1)*8 + lr;
        const int ks2 = g & 1;

        #pragma unroll
        for (int ki = 0; ki < 4; ki++) {
            uint32_t ahf[4][4], alf[4][4];
            #pragma unroll
            for (int fm = 0; fm < 4; fm++) {
                uint32_t off = SWZ128((uint32_t)((wm*64 + fm*16 + lrow)*128 + ki*32 + kseg*16));
                LDSM_X4(ahf[fm][0], ahf[fm][1], ahf[fm][2], ahf[fm][3], sbb + off);
                LDSM_X4(alf[fm][0], alf[fm][1], alf[fm][2], alf[fm][3], sbb + 16384u + off);
            }
            uint32_t bhf[4][2], blf[4][2];
            #pragma unroll
            for (int fp = 0; fp < 2; fp++) {
                uint32_t off = SWZ128((uint32_t)((wn*32 + fp*16 + nrow)*128 + ki*32 + ks2*16));
                LDSM_X4(bhf[fp*2][0], bhf[fp*2][1], bhf[fp*2+1][0], bhf[fp*2+1][1], sbb + 32768u + off);
                LDSM_X4(blf[fp*2][0], blf[fp*2][1], blf[fp*2+1][0], blf[fp*2+1][1], sbb + 49152u + off);
            }
            #pragma unroll
            for (int fm = 0; fm < 4; fm++)
            #pragma unroll
            for (int fn = 0; fn < 4; fn++) {
                mma16816(c[fm][fn], ahf[fm], bhf[fn]);
                mma16816(c[fm][fn], ahf[fm], blf[fn]);
                mma16816(c[fm][fn], alf[fm], bhf[fn]);
            }
        }
        __syncthreads();
    }

    const int l4 = lane >> 2;
    const int l2 = (lane & 3)*2;
    #pragma unroll
    for (int fm = 0; fm < 4; fm++) {
        const int mr0 = wm*64 + fm*16 + l4;
        #pragma unroll
        for (int fn = 0; fn < 4; fn++) {
            const int col = wn*32 + fn*8 + l2;
            if (MODE == 0) {
                const int gcol = blockIdx.y*128 + col;
                float2 bv = *(const float2*)(bias + blockIdx.z*768 + gcol);
                size_t m0 = (size_t)blockIdx.z*131072 + (size_t)blockIdx.x*128 + mr0;
                *(float2*)(outp + m0*768 + gcol)       = make_float2(c[fm][fn][0] + bv.x, c[fm][fn][1] + bv.y);
                *(float2*)(outp + (m0 + 8)*768 + gcol) = make_float2(c[fm][fn][2] + bv.x, c[fm][fn][3] + bv.y);
            } else {
                size_t m0 = (size_t)blockIdx.z*256 + (size_t)blockIdx.x*128 + mr0;
                *(float2*)(outp + m0*128 + col)       = make_float2(c[fm][fn][0], c[fm][fn][1]);
                *(float2*)(outp + (m0 + 8)*128 + col) = make_float2(c[fm][fn][2], c[fm][fn][3]);
            }
        }
    }
}

// ---------------- final reduce + MLP head ----------------
__global__ void __launch_bounds__(128) fc_reduce_kernel(
    const float* __restrict__ b1, const float* __restrict__ W2,
    const float* __restrict__ b2, float* __restrict__ out) {
    const int b = blockIdx.x;
    const int o = threadIdx.x;
    const float* p = d_fc1p + (size_t)b*128 + o;
    float s0 = 0.f, s1 = 0.f, s2 = 0.f, s3 = 0.f;
    #pragma unroll 4
    for (int t = 0; t < 512; t += 4) {
        s0 += p[(size_t)(t+0)*32768];
        s1 += p[(size_t)(t+1)*32768];
        s2 += p[(size_t)(t+2)*32768];
        s3 += p[(size_t)(t+3)*32768];
    }
    float s = b1[o] + ((s0 + s1) + (s2 + s3));
    float v = s > 0.f ? s : 0.01f*s;
    float c = v * __ldg(W2 + o);
    __shared__ float red[128];
    red[o] = c;
    __syncthreads();
    for (int st = 64; st > 0; st >>= 1) {
        if (o < st) red[o] += red[o + st];
        __syncthreads();
    }
    if (o == 0) out[b] = 1.f/(1.f + expf(-(red[0] + b2[0])));
}

// ---------------- launch ----------------
extern "C" void kernel_launch(void* const* d_in, const int* in_sizes, int n_in,
                              void* d_out, int out_size) {
    const int*   inputs = (const int*)  d_in[0];
    const float* emb    = (const float*)d_in[1];
    const float* wih0   = (const float*)d_in[2];
    const float* whh0   = (const float*)d_in[3];
    const float* bih0   = (const float*)d_in[4];
    const float* bhh0   = (const float*)d_in[5];
    const float* wih1   = (const float*)d_in[6];
    const float* whh1   = (const float*)d_in[7];
    const float* bih1   = (const float*)d_in[8];
    const float* bhh1   = (const float*)d_in[9];
    const float* W1     = (const float*)d_in[10];
    const float* b1     = (const float*)d_in[11];
    const float* W2     = (const float*)d_in[12];
    const float* b2     = (const float*)d_in[13];
    float* out = (float*)d_out;

    cudaFuncSetAttribute((const void*)rec_mma_kernel<0>,
                         cudaFuncAttributeMaxDynamicSharedMemorySize, RECM_SMEM);
    cudaFuncSetAttribute((const void*)rec_mma_kernel<1>,
                         cudaFuncAttributeMaxDynamicSharedMemorySize, RECM_SMEM);
    cudaFuncSetAttribute((const void*)mma_gemm_kernel<0>,
                         cudaFuncAttributeMaxDynamicSharedMemorySize, MMA_DSMEM);
    cudaFuncSetAttribute((const void*)mma_gemm_kernel<1>,
                         cudaFuncAttributeMaxDynamicSharedMemorySize, MMA_DSMEM);

    __nv_bfloat16 *h1hi, *h1lo, *h2hi, *h2lo, *wihhi, *wihlo, *W1hi, *W1lo;
    cudaGetSymbolAddress((void**)&h1hi, d_h1hi);
    cudaGetSymbolAddress((void**)&h1lo, d_h1lo);
    cudaGetSymbolAddress((void**)&h2hi, d_h2hi);
    cudaGetSymbolAddress((void**)&h2lo, d_h2lo);
    cudaGetSymbolAddress((void**)&wihhi, d_wihhi);
    cudaGetSymbolAddress((void**)&wihlo, d_wihlo);
    cudaGetSymbolAddress((void**)&W1hi, d_W1hi);
    cudaGetSymbolAddress((void**)&W1lo, d_W1lo);
    float *xp1p, *fc1p;
    cudaGetSymbolAddress((void**)&xp1p, d_xp1);
    cudaGetSymbolAddress((void**)&fc1p, d_fc1p);

    proj0_kernel<<<130, 256>>>(emb, wih0, bih0);
    split_kernel<<<768, 256>>>(wih1, wihhi, wihlo, 196608);
    split_kernel<<<4096, 256>>>(W1, W1hi, W1lo, 8388608);
    reset_bar_kernel<<<16, 256>>>();
    rec_mma_kernel<0><<<128, 256, RECM_SMEM>>>(inputs, whh0, bhh0);
    mma_gemm_kernel<0><<<dim3(1024, 6, 2), 256, MMA_DSMEM>>>(h1hi, h1lo, wihhi, wihlo, bih1, xp1p);
    rec_mma_kernel<1><<<128, 256, RECM_SMEM>>>(inputs, whh1, bhh1);
    mma_gemm_kernel<1><<<dim3(2, 1, 512), 256, MMA_DSMEM>>>(h2hi, h2lo, W1hi, W1lo, nullptr, fc1p);
    fc_reduce_kernel<<<256, 128>>>(b1, W2, b2, out);
}

// round 16
// speedup vs baseline: 1.3967x; 1.2298x over previous
#include <cuda_runtime.h>
#include <cuda_fp16.h>
#include <math.h>
#include <stddef.h>
#include <stdint.h>

// B=256, T=512, V=64(65 rows), E=128, H=256, 3H=768, D=2

// ---------------- PTX helpers (baseline ISA only: sm_80-era, safe on sm_103) ----------------
__device__ __forceinline__ uint32_t smem_to_u32(const void* p) {
    uint32_t a;
    asm("{ .reg .u64 t; cvta.to.shared.u64 t, %1; cvt.u32.u64 %0, t; }" : "=r"(a) : "l"(p));
    return a;
}
__device__ __forceinline__ void cp16(uint32_t s, const void* g) {
    asm volatile("cp.async.cg.shared.global [%0], [%1], 16;" :: "r"(s), "l"(g) : "memory");
}
#define CP_COMMIT() asm volatile("cp.async.commit_group;" ::: "memory")
#define CP_WAIT(n)  asm volatile("cp.async.wait_group %0;" :: "n"(n) : "memory")
#define LDSM_X4(r0, r1, r2, r3, addr) \
    asm volatile("ldmatrix.sync.aligned.m8n8.x4.shared.b16 {%0,%1,%2,%3}, [%4];" \
        : "=r"(r0), "=r"(r1), "=r"(r2), "=r"(r3) : "r"(addr))
#define LDSM_X2(r0, r1, addr) \
    asm volatile("ldmatrix.sync.aligned.m8n8.x2.shared.b16 {%0,%1}, [%2];" \
        : "=r"(r0), "=r"(r1) : "r"(addr))

// fp16 MMA, fp32 accumulate
__device__ __forceinline__ void mma16816h(float* c, const uint32_t* a, const uint32_t* b) {
    asm volatile(
        "mma.sync.aligned.m16n8k16.row.col.f32.f16.f16.f32 "
        "{%0,%1,%2,%3}, {%4,%5,%6,%7}, {%8,%9}, {%0,%1,%2,%3};"
        : "+f"(c[0]), "+f"(c[1]), "+f"(c[2]), "+f"(c[3])
        : "r"(a[0]), "r"(a[1]), "r"(a[2]), "r"(a[3]), "r"(b[0]), "r"(b[1]));
}

#define SWZ128(b) ((b) ^ (((b) >> 3) & 0x70))

// pack 4 floats -> hi/lo fp16 pairs (8 bytes each)
__device__ __forceinline__ void split4h(float4 v, uint2& hi, uint2& lo) {
    __half a0 = __float2half_rn(v.x), a1 = __float2half_rn(v.y);
    __half a2 = __float2half_rn(v.z), a3 = __float2half_rn(v.w);
    __half l0 = __float2half_rn(v.x - __half2float(a0));
    __half l1 = __float2half_rn(v.y - __half2float(a1));
    __half l2 = __float2half_rn(v.z - __half2float(a2));
    __half l3 = __float2half_rn(v.w - __half2float(a3));
    __half2 h01 = __halves2half2(a0, a1), h23 = __halves2half2(a2, a3);
    __half2 m01 = __halves2half2(l0, l1), m23 = __halves2half2(l2, l3);
    hi.x = *(uint32_t*)&h01; hi.y = *(uint32_t*)&h23;
    lo.x = *(uint32_t*)&m01; lo.y = *(uint32_t*)&m23;
}

__device__ __forceinline__ float tanh_ap(float x) {
    float y;
    asm("tanh.approx.f32 %0, %1;" : "=f"(y) : "f"(x));
    return y;
}
__device__ __forceinline__ float fsig(float x) {
    return fmaf(tanh_ap(0.5f*x), 0.5f, 0.5f);
}
__device__ __forceinline__ float ftanh(float x) {
    return __fdividef(2.f, 1.f + __expf(-2.f*x)) - 1.f;
}

// ---------------- static scratch ----------------
__device__ float d_ptab [2*65*768];
__device__ float d_xp1  [2*512*256*768];
__device__ float d_fc1p [512*256*128];
__device__ __half d_h1f[67108864];     // layer-0 output, single fp16 [t][b][2H]
__device__ __half d_h2f[67108864];     // layer-1 output, single fp16
__device__ __half d_wihh[786432], d_wihl[786432];
__device__ __half d_W1h[33554432], d_W1l[33554432];
__device__ unsigned d_flags[4096];     // [16 groups][8 slots][32 pad]

__global__ void reset_bar_kernel() {
    d_flags[blockIdx.x*256 + threadIdx.x] = 0u;
}

// consumer-side poll: 8 lanes poll the 8 peer flags of the group
__device__ __forceinline__ void poll_group(int gid, unsigned target, int lane) {
    if (lane < 8) {
        const unsigned* f = d_flags + (gid*8 + lane)*32;
        unsigned v;
        while (true) {
            asm volatile("ld.global.acquire.gpu.u32 %0, [%1];" : "=r"(v) : "l"(f));
            if (v >= target) break;
            __nanosleep(20);
        }
    }
    __syncwarp();
}

// ---------------- L0 proj table ----------------
__global__ void __launch_bounds__(256) proj0_kernel(const float* __restrict__ emb,
                                                    const float* __restrict__ wih,
                                                    const float* __restrict__ bih) {
    const int d = blockIdx.x / 65;
    const int v = blockIdx.x % 65;
    __shared__ float es[128];
    if (threadIdx.x < 128) es[threadIdx.x] = emb[v*128 + threadIdx.x];
    __syncthreads();
    for (int g = threadIdx.x; g < 768; g += 256) {
        const float* w = wih + ((size_t)d*768 + g)*128;
        float s = bih[d*768 + g];
        #pragma unroll 4
        for (int e = 0; e < 128; e++) s += es[e]*__ldg(w + e);
        d_ptab[((size_t)d*65 + v)*768 + g] = s;
    }
}

// ---------------- fp32 -> fp16 hi/lo split (weights) ----------------
__global__ void __launch_bounds__(256) split_kernel(const float* __restrict__ x,
        __half* __restrict__ hi, __half* __restrict__ lo, size_t n4) {
    size_t i = (size_t)blockIdx.x*256 + threadIdx.x;
    size_t stride = (size_t)gridDim.x*256;
    for (; i < n4; i += stride) {
        float4 v = __ldg((const float4*)x + i);
        uint2 h, l;
        split4h(v, h, l);
        ((uint2*)hi)[i] = h;
        ((uint2*)lo)[i] = l;
    }
}

// ---------------- MMA recurrence (both layers) ----------------
// 128 CTAs = dir(2) x batch-slice(8 x 32 rows) x unit-slice(8 x 32 units)
// Per step: G[32 x 96] = h[32 x 256] @ (Whi+Wlo)[96 x 256]^T, 2-pass fp16 mma
// (h single fp16; W fp16 hi/lo; W-hi fragments hoisted to registers).
// SMEM (1024-aligned base):
//   WHI @ 0      : 49152 (init preload only)
//   WLO @ 49152  : 49152
//   HF  @ 98304  : 16384 (single fp16 h tile, 4 chunks x 32rows x 128B)
//   G   @ 114688 : 32 x 100 floats = 12800
//   HPREV@127488 : 32 x 36 floats  = 4608
#define RECM_SMEM (132096 + 1024)

template<int LAYER>
__global__ void __launch_bounds__(256, 1) rec_mma_kernel(
    const int* __restrict__ inputs,
    const float* __restrict__ w_hh,
    const float* __restrict__ b_hh) {
    extern __shared__ char sm_raw[];
    __shared__ float bhh_s[96];
    const uint32_t raw  = smem_to_u32(sm_raw);
    const uint32_t base = (raw + 1023u) & ~1023u;
    char* sb = sm_raw + (base - raw);
    float* Gs    = (float*)(sb + 114688);
    float* Hprev = (float*)(sb + 127488);

    const int bid = blockIdx.x;
    const int dir = bid >> 6;
    const int rem = bid & 63;
    const int bs  = rem >> 3;
    const int us  = rem & 7;
    const int b0  = bs * 32;
    const int j0  = us * 32;
    const int gid = dir*8 + bs;
    const int tid = threadIdx.x;
    const int lane = tid & 31;
    const int wid  = tid >> 5;

    // ---- one-time: W_hh slice -> fp16 hi/lo swizzled smem (gate-major rows) ----
    {
        const int k0 = (tid & 7) * 32;
        #pragma unroll
        for (int rr = 0; rr < 3; rr++) {
            const int lr = rr*32 + (tid >> 3);
            const int g  = lr >> 5;
            const float* src = w_hh + ((size_t)dir*768 + g*256 + j0 + (lr & 31))*256 + k0;
            const uint32_t cb = (uint32_t)(k0 >> 6)*12288u + (uint32_t)lr*128u + (uint32_t)(k0 & 63)*2u;
            #pragma unroll
            for (int q = 0; q < 8; q++) {
                float4 v = __ldg((const float4*)src + q);
                uint2 h, l;
                split4h(v, h, l);
                uint32_t off = SWZ128(cb + q*8);
                *(uint2*)(sb + off)          = h;
                *(uint2*)(sb + 49152u + off) = l;
            }
        }
    }
    if (tid < 96) bhh_s[tid] = b_hh[dir*768 + (tid>>5)*256 + j0 + (tid & 31)];
    // zero h tile + hprev
    for (int i = tid; i < 1024; i += 256)
        ((uint4*)(sb + 98304))[i] = make_uint4(0,0,0,0);
    for (int i = tid; i < 1152; i += 256)
        Hprev[i] = 0.f;
    __syncthreads();

    // per-thread nonlinearity mapping
    const int bb = tid >> 3;
    const int ju = (tid & 7) * 4;
    const int bg = b0 + bb;

    // MMA lane mappings
    const int wm = wid >> 2, wn = wid & 3;
    const int lrow = lane & 15, kseg = lane >> 4;
    const int g8 = lane >> 3, lr8 = lane & 7;
    const int nrx4 = ((g8 >> 1) & 1)*8 + lr8;
    const int ksx4 = g8 & 1;
    const int lx = lane & 15;
    const int rowb2 = lx & 7, kh2 = (lx >> 3) & 1;

    // ---- hoist W-hi B-fragments into registers (step-invariant, 96 regs) ----
    uint32_t Bh4[16][4], Bh2[16][2];
    #pragma unroll
    for (int ks = 0; ks < 16; ks++) {
        const int ck = ks >> 2, ki = ks & 3;
        const uint32_t bcb = base + (uint32_t)ck*12288u;
        const uint32_t b4 = bcb +
            SWZ128((uint32_t)((wn*24 + nrx4)*128 + ki*32 + ksx4*16));
        const uint32_t b2 = bcb +
            SWZ128((uint32_t)((wn*24 + 16 + rowb2)*128 + ki*32 + kh2*16));
        LDSM_X4(Bh4[ks][0], Bh4[ks][1], Bh4[ks][2], Bh4[ks][3], b4);
        LDSM_X2(Bh2[ks][0], Bh2[ks][1], b2);
    }

    __half* obf = (LAYER == 0) ? d_h1f : d_h2f;
    const unsigned LB = (unsigned)(LAYER * 512);

    for (int s_ = 0; s_ < 512; s_++) {
        // prefetch x-projections (independent of peers -> issue before poll)
        const int t_in = (dir == 0) ? s_ : (511 - s_);
        float4 xr4, xz4, xn4;
        if (LAYER == 0) {
            const int tok = __ldg(inputs + bg*512 + t_in);
            const float* pt = d_ptab + ((size_t)dir*65 + tok)*768 + j0 + ju;
            xr4 = __ldg((const float4*)(pt));
            xz4 = __ldg((const float4*)(pt + 256));
            xn4 = __ldg((const float4*)(pt + 512));
        } else {
            const float* xp = d_xp1 + ((size_t)dir*131072 + (size_t)t_in*256 + bg)*768 + j0 + ju;
            xr4 = __ldg((const float4*)(xp));
            xz4 = __ldg((const float4*)(xp + 256));
            xn4 = __ldg((const float4*)(xp + 512));
        }

        if (s_ > 0) {
            poll_group(gid, LB + (unsigned)s_, lane);
            // read peers' h (single fp16) from output buffer at t_prev (row stride 512)
            const int t_prev = (dir == 0) ? (s_ - 1) : (512 - s_);
            const __half* ghf = obf + ((size_t)t_prev*256 + b0)*512 + (size_t)dir*256;
            const int r  = tid >> 3;            // 0..31 (batch row)
            const int sg = tid & 7;             // 16B segment within 64-col chunk
            #pragma unroll
            for (int ck = 0; ck < 4; ck++) {
                uint32_t dst = SWZ128((uint32_t)(ck*4096 + r*128 + sg*16));
                size_t gofs = (size_t)r*512 + (size_t)ck*64 + (size_t)sg*8;
                cp16(base + 98304u + dst, ghf + gofs);
                if (ck == 1) CP_COMMIT();
            }
            CP_COMMIT();
        }

        // ---- MMA: G = h @ (Whi+Wlo)^T, 2-pass fp16 ----
        float c[3][4];
        #pragma unroll
        for (int fn = 0; fn < 3; fn++)
            #pragma unroll
            for (int q = 0; q < 4; q++) c[fn][q] = 0.f;

        #pragma unroll
        for (int half = 0; half < 2; half++) {
            if (s_ > 0) { if (half == 0) { CP_WAIT(1); } else { CP_WAIT(0); } }
            __syncthreads();
            #pragma unroll
            for (int ks8 = 0; ks8 < 8; ks8++) {
                const int ks = half*8 + ks8;
                const int ck = ks >> 2, ki = ks & 3;
                const uint32_t ain = base + 98304u + (uint32_t)ck*4096u +
                    SWZ128((uint32_t)((wm*16 + lrow)*128 + ki*32 + kseg*16));
                uint32_t ah[4];
                LDSM_X4(ah[0], ah[1], ah[2], ah[3], ain);
                const uint32_t bcb = base + 49152u + (uint32_t)ck*12288u;
                const uint32_t b4l = bcb +
                    SWZ128((uint32_t)((wn*24 + nrx4)*128 + ki*32 + ksx4*16));
                const uint32_t b2l = bcb +
                    SWZ128((uint32_t)((wn*24 + 16 + rowb2)*128 + ki*32 + kh2*16));
                uint32_t bl[3][2];
                LDSM_X4(bl[0][0], bl[0][1], bl[1][0], bl[1][1], b4l);
                LDSM_X2(bl[2][0], bl[2][1], b2l);
                uint32_t bh0[2] = {Bh4[ks][0], Bh4[ks][1]};
                uint32_t bh1[2] = {Bh4[ks][2], Bh4[ks][3]};
                uint32_t bh2v[2] = {Bh2[ks][0], Bh2[ks][1]};
                mma16816h(c[0], ah, bh0);
                mma16816h(c[1], ah, bh1);
                mma16816h(c[2], ah, bh2v);
                #pragma unroll
                for (int fn = 0; fn < 3; fn++)
                    mma16816h(c[fn], ah, bl[fn]);
            }
        }

        // write G to smem
        {
            const int l4 = lane >> 2, l2 = (lane & 3)*2;
            #pragma unroll
            for (int fn = 0; fn < 3; fn++) {
                const int col = wn*24 + fn*8 + l2;
                *(float2*)&Gs[(wm*16 + l4)*100 + col]     = make_float2(c[fn][0], c[fn][1]);
                *(float2*)&Gs[(wm*16 + l4 + 8)*100 + col] = make_float2(c[fn][2], c[fn][3]);
            }
        }
        __syncthreads();

        // ---- nonlinearity + h update ----
        {
            float4 gr = *(const float4*)&Gs[bb*100 + ju];
            float4 gz = *(const float4*)&Gs[bb*100 + 32 + ju];
            float4 gn = *(const float4*)&Gs[bb*100 + 64 + ju];
            float4 hp = *(const float4*)&Hprev[bb*36 + ju];
            float hn[4];
            const float* xr = &xr4.x;
            const float* xz = &xz4.x;
            const float* xn = &xn4.x;
            const float* grp = &gr.x;
            const float* gzp = &gz.x;
            const float* gnp = &gn.x;
            const float* hpp = &hp.x;
            #pragma unroll
            for (int i = 0; i < 4; i++) {
                float r = fsig(xr[i] + grp[i] + bhh_s[     ju + i]);
                float z = fsig(xz[i] + gzp[i] + bhh_s[32 + ju + i]);
                float n = ftanh(xn[i] + r*(gnp[i] + bhh_s[64 + ju + i]));
                hn[i] = (1.f - z)*n + z*hpp[i];
            }
            float4 hv = make_float4(hn[0], hn[1], hn[2], hn[3]);
            *(float4*)&Hprev[bb*36 + ju] = hv;
            __half2 h01 = __floats2half2_rn(hn[0], hn[1]);
            __half2 h23 = __floats2half2_rn(hn[2], hn[3]);
            uint32_t w0 = *(uint32_t*)&h01, w1 = *(uint32_t*)&h23;
            size_t oo = ((size_t)t_in*256 + bg)*512 + (size_t)dir*256 + j0 + ju;
            asm volatile("st.global.cg.v2.u32 [%0], {%1,%2};" :: "l"(obf + oo), "r"(w0), "r"(w1));
        }
        if (s_ != 511) {
            __syncthreads();
            if (tid == 0) {
                asm volatile("st.global.release.gpu.u32 [%0], %1;"
                    :: "l"(d_flags + (gid*8 + us)*32), "r"(LB + (unsigned)(s_ + 1)));
            }
        }
    }
}

// ---------------- 2-pass fp16 warp-MMA GEMM ----------------
// C = A @ (Bhi+Blo)^T, A single fp16, fp32 accum.
// MODE 0: xp1 = h1f @ wih1^T + bias.  grid (1024 mtiles, 6 ntiles, 2 dirs)
// MODE 1: fc1 partials per t.         grid (2 mtiles, 1, 512 t)
#define MMA_DSMEM (2*49152 + 1024)

template<int MODE>
__global__ void __launch_bounds__(256) mma_gemm_kernel(
    const __half* __restrict__ Af,
    const __half* __restrict__ Bh, const __half* __restrict__ Bl,
    const float* __restrict__ bias, float* __restrict__ outp) {
    extern __shared__ char dsm_raw[];
    const uint32_t raw  = smem_to_u32(dsm_raw);
    const uint32_t base = (raw + 1023u) & ~1023u;

    const int tid  = threadIdx.x;
    const int lane = tid & 31;
    const int wid  = tid >> 5;
    const int wm   = wid >> 2;
    const int wn   = wid & 3;

    size_t arow0, brow0, bstride, bk0;
    if (MODE == 0) {
        arow0 = (size_t)blockIdx.x * 128;
        brow0 = (size_t)blockIdx.z * 768 + (size_t)blockIdx.y * 128;
        bstride = 512; bk0 = 0;
    } else {
        arow0 = (size_t)blockIdx.z * 256 + (size_t)blockIdx.x * 128;
        brow0 = 0;
        bstride = 262144; bk0 = (size_t)blockIdx.z * 512;
    }

    float c[4][4][4];
    #pragma unroll
    for (int fm = 0; fm < 4; fm++)
    #pragma unroll
    for (int fn = 0; fn < 4; fn++)
    #pragma unroll
    for (int q = 0; q < 4; q++) c[fm][fn][q] = 0.f;

    auto issue = [&](int kc, int buf) {
        const uint32_t sbb = base + (uint32_t)buf*49152u;
        #pragma unroll
        for (int v = 0; v < 4; v++) {
            int vv = tid + v*256;
            int r = vv >> 3, seg = vv & 7;
            uint32_t sw = SWZ128((uint32_t)(r*128 + seg*16));
            size_t k  = (size_t)kc*64 + (size_t)seg*8;
            size_t ga = (arow0 + r)*512 + k;
            size_t gb = (brow0 + r)*bstride + bk0 + k;
            cp16(sbb +          sw, Af + ga);
            cp16(sbb + 16384u + sw, Bh + gb);
            cp16(sbb + 32768u + sw, Bl + gb);
        }
    };

    issue(0, 0); CP_COMMIT();

    for (int kc = 0; kc < 8; kc++) {
        if (kc < 7) {
            issue(kc + 1, (kc + 1) & 1); CP_COMMIT();
            CP_WAIT(1);
        } else {
            CP_WAIT(0);
        }
        __syncthreads();

        const uint32_t sbb = base + (uint32_t)(kc & 1)*49152u;
        const int lrow = lane & 15, kseg = lane >> 4;
        const int g = lane >> 3, lr = lane & 7;
        const int nrow = ((g >> 1) & 1)*8 + lr;
        const int ks2 = g & 1;

        #pragma unroll
        for (int ki = 0; ki < 4; ki++) {
            uint32_t ahf[4][4];
            #pragma unroll
            for (int fm = 0; fm < 4; fm++) {
                uint32_t off = SWZ128((uint32_t)((wm*64 + fm*16 + lrow)*128 + ki*32 + kseg*16));
                LDSM_X4(ahf[fm][0], ahf[fm][1], ahf[fm][2], ahf[fm][3], sbb + off);
            }
            uint32_t bhf[4][2], blf[4][2];
            #pragma unroll
            for (int fp = 0; fp < 2; fp++) {
                uint32_t off = SWZ128((uint32_t)((wn*32 + fp*16 + nrow)*128 + ki*32 + ks2*16));
                LDSM_X4(bhf[fp*2][0], bhf[fp*2][1], bhf[fp*2+1][0], bhf[fp*2+1][1], sbb + 16384u + off);
                LDSM_X4(blf[fp*2][0], blf[fp*2][1], blf[fp*2+1][0], blf[fp*2+1][1], sbb + 32768u + off);
            }
            #pragma unroll
            for (int fm = 0; fm < 4; fm++)
            #pragma unroll
            for (int fn = 0; fn < 4; fn++) {
                mma16816h(c[fm][fn], ahf[fm], bhf[fn]);
                mma16816h(c[fm][fn], ahf[fm], blf[fn]);
            }
        }
        __syncthreads();
    }

    const int l4 = lane >> 2;
    const int l2 = (lane & 3)*2;
    #pragma unroll
    for (int fm = 0; fm < 4; fm++) {
        const int mr0 = wm*64 + fm*16 + l4;
        #pragma unroll
        for (int fn = 0; fn < 4; fn++) {
            const int col = wn*32 + fn*8 + l2;
            if (MODE == 0) {
                const int gcol = blockIdx.y*128 + col;
                float2 bv = *(const float2*)(bias + blockIdx.z*768 + gcol);
                size_t m0 = (size_t)blockIdx.z*131072 + (size_t)blockIdx.x*128 + mr0;
                *(float2*)(outp + m0*768 + gcol)       = make_float2(c[fm][fn][0] + bv.x, c[fm][fn][1] + bv.y);
                *(float2*)(outp + (m0 + 8)*768 + gcol) = make_float2(c[fm][fn][2] + bv.x, c[fm][fn][3] + bv.y);
            } else {
                size_t m0 = (size_t)blockIdx.z*256 + (size_t)blockIdx.x*128 + mr0;
                *(float2*)(outp + m0*128 + col)       = make_float2(c[fm][fn][0], c[fm][fn][1]);
                *(float2*)(outp + (m0 + 8)*128 + col) = make_float2(c[fm][fn][2], c[fm][fn][3]);
            }
        }
    }
}

// ---------------- final reduce + MLP head ----------------
__global__ void __launch_bounds__(128) fc_reduce_kernel(
    const float* __restrict__ b1, const float* __restrict__ W2,
    const float* __restrict__ b2, float* __restrict__ out) {
    const int b = blockIdx.x;
    const int o = threadIdx.x;
    const float* p = d_fc1p + (size_t)b*128 + o;
    float s0 = 0.f, s1 = 0.f, s2 = 0.f, s3 = 0.f;
    #pragma unroll 4
    for (int t = 0; t < 512; t += 4) {
        s0 += p[(size_t)(t+0)*32768];
        s1 += p[(size_t)(t+1)*32768];
        s2 += p[(size_t)(t+2)*32768];
        s3 += p[(size_t)(t+3)*32768];
    }
    float s = b1[o] + ((s0 + s1) + (s2 + s3));
    float v = s > 0.f ? s : 0.01f*s;
    float c = v * __ldg(W2 + o);
    __shared__ float red[128];
    red[o] = c;
    __syncthreads();
    for (int st = 64; st > 0; st >>= 1) {
        if (o < st) red[o] += red[o + st];
        __syncthreads();
    }
    if (o == 0) out[b] = 1.f/(1.f + expf(-(red[0] + b2[0])));
}

// ---------------- launch ----------------
extern "C" void kernel_launch(void* const* d_in, const int* in_sizes, int n_in,
                              void* d_out, int out_size) {
    const int*   inputs = (const int*)  d_in[0];
    const float* emb    = (const float*)d_in[1];
    const float* wih0   = (const float*)d_in[2];
    const float* whh0   = (const float*)d_in[3];
    const float* bih0   = (const float*)d_in[4];
    const float* bhh0   = (const float*)d_in[5];
    const float* wih1   = (const float*)d_in[6];
    const float* whh1   = (const float*)d_in[7];
    const float* bih1   = (const float*)d_in[8];
    const float* bhh1   = (const float*)d_in[9];
    const float* W1     = (const float*)d_in[10];
    const float* b1     = (const float*)d_in[11];
    const float* W2     = (const float*)d_in[12];
    const float* b2     = (const float*)d_in[13];
    float* out = (float*)d_out;

    cudaFuncSetAttribute((const void*)rec_mma_kernel<0>,
                         cudaFuncAttributeMaxDynamicSharedMemorySize, RECM_SMEM);
    cudaFuncSetAttribute((const void*)rec_mma_kernel<1>,
                         cudaFuncAttributeMaxDynamicSharedMemorySize, RECM_SMEM);
    cudaFuncSetAttribute((const void*)mma_gemm_kernel<0>,
                         cudaFuncAttributeMaxDynamicSharedMemorySize, MMA_DSMEM);
    cudaFuncSetAttribute((const void*)mma_gemm_kernel<1>,
                         cudaFuncAttributeMaxDynamicSharedMemorySize, MMA_DSMEM);

    __half *h1f, *h2f, *wihh, *wihl, *W1h, *W1l;
    cudaGetSymbolAddress((void**)&h1f, d_h1f);
    cudaGetSymbolAddress((void**)&h2f, d_h2f);
    cudaGetSymbolAddress((void**)&wihh, d_wihh);
    cudaGetSymbolAddress((void**)&wihl, d_wihl);
    cudaGetSymbolAddress((void**)&W1h, d_W1h);
    cudaGetSymbolAddress((void**)&W1l, d_W1l);
    float *xp1p, *fc1p;
    cudaGetSymbolAddress((void**)&xp1p, d_xp1);
    cudaGetSymbolAddress((void**)&fc1p, d_fc1p);

    proj0_kernel<<<130, 256>>>(emb, wih0, bih0);
    split_kernel<<<768, 256>>>(wih1, wihh, wihl, 196608);
    split_kernel<<<4096, 256>>>(W1, W1h, W1l, 8388608);
    reset_bar_kernel<<<16, 256>>>();
    rec_mma_kernel<0><<<128, 256, RECM_SMEM>>>(inputs, whh0, bhh0);
    mma_gemm_kernel<0><<<dim3(1024, 6, 2), 256, MMA_DSMEM>>>(h1f, wihh, wihl, bih1, xp1p);
    rec_mma_kernel<1><<<128, 256, RECM_SMEM>>>(inputs, whh1, bhh1);
    mma_gemm_kernel<1><<<dim3(2, 1, 512), 256, MMA_DSMEM>>>(h2f, W1h, W1l, nullptr, fc1p);
    fc_reduce_kernel<<<256, 128>>>(b1, W2, b2, out);
}